// round 2
// baseline (speedup 1.0000x reference)
#include <cuda_runtime.h>
#include <math.h>

#define BB    8
#define NPG   5000      // nodes per graph
#define EPG   80000     // edges per graph
#define NN    40000     // B*N
#define GE    640000    // B*E
#define NODE_IN 32
#define EDGE_IN 16
#define HID   128
#define EMB   64

// ---------------- scratch (static device arrays; no allocation) -------------
__device__ float d_nx[NN * NODE_IN];        // layernormed node features
__device__ float d_nef[GE * EDGE_IN];       // layernormed edge features
__device__ float d_ee0[GE];                 // edge logit term layer0 (ef . wae0)
__device__ float d_ee1[GE];                 // edge logit term layer1
__device__ int   d_gsrc[GE];                // global src index per global edge
__device__ int   d_off[NN + 1];             // CSR offsets (also degree counter)
__device__ int   d_cur[NN];                 // scatter cursors
__device__ int   d_csr[GE];                 // edge ids sorted by dst
__device__ float d_h0[NN * HID];            // layer0 projected features
__device__ float d_s0s[NN], d_s0d[NN];
__device__ float d_g0[NN * HID];            // elu(gat0 out)
__device__ float d_h1[NN * EMB];
__device__ float d_s1s[NN], d_s1d[NN];
__device__ float d_emb[NN * EMB];           // node_emb
__device__ float d_A[NN * HID];             // emb @ W1[0:64]
__device__ float d_Bm[NN * HID];            // emb @ W1[64:128]
__device__ float d_D[BB * HID];             // ctx @ W1[144:272] + b1
__device__ float d_wae0[EDGE_IN], d_wae1[EDGE_IN];

// ---------------- k_pre: zero degree array + compute wae vectors -----------
__global__ void k_pre(const float* __restrict__ We0, const float* __restrict__ ae0,
                      const float* __restrict__ We1, const float* __restrict__ ae1)
{
    int t = blockIdx.x * blockDim.x + threadIdx.x;
    for (int i = t; i <= NN; i += gridDim.x * blockDim.x) d_off[i] = 0;
    if (blockIdx.x == 0) {
        int tt = threadIdx.x;
        if (tt < EDGE_IN) {
            float s = 0.f;
            for (int c = 0; c < HID; c++) s += We0[tt * HID + c] * ae0[c];
            d_wae0[tt] = s;
        } else if (tt < 2 * EDGE_IN) {
            int k = tt - EDGE_IN;
            float s = 0.f;
            for (int c = 0; c < EMB; c++) s += We1[k * EMB + c] * ae1[c];
            d_wae1[k] = s;
        }
    }
}

// ---------------- node layernorm: warp per node (32 channels) --------------
__global__ void k_ln_node(const float* __restrict__ x, const float* __restrict__ g,
                          const float* __restrict__ b)
{
    int warp = threadIdx.x >> 5, lane = threadIdx.x & 31;
    int n = blockIdx.x * 8 + warp;
    if (n >= NN) return;
    float v = x[n * 32 + lane];
    float mu = v;
    #pragma unroll
    for (int o = 16; o; o >>= 1) mu += __shfl_xor_sync(~0u, mu, o);
    mu *= (1.f / 32.f);
    float d = v - mu;
    float var = d * d;
    #pragma unroll
    for (int o = 16; o; o >>= 1) var += __shfl_xor_sync(~0u, var, o);
    var *= (1.f / 32.f);
    d_nx[n * 32 + lane] = d * rsqrtf(var + 1e-5f) * g[lane] + b[lane];
}

// ------------- edge layernorm + logit terms + gsrc + degree count ----------
__global__ void k_ln_edge(const float* __restrict__ ea, const float* __restrict__ g,
                          const float* __restrict__ b, const int* __restrict__ ei)
{
    int ge = blockIdx.x * 256 + threadIdx.x;
    if (ge >= GE) return;
    int bb = ge / EPG;
    int e  = ge - bb * EPG;
    int src = ei[e] + bb * NPG;
    int dst = ei[EPG + e] + bb * NPG;
    d_gsrc[ge] = src;
    atomicAdd(&d_off[dst], 1);

    const float* row = ea + (size_t)ge * EDGE_IN;
    float v[EDGE_IN];
    float mu = 0.f;
    #pragma unroll
    for (int k = 0; k < EDGE_IN; k++) { v[k] = row[k]; mu += v[k]; }
    mu *= (1.f / EDGE_IN);
    float var = 0.f;
    #pragma unroll
    for (int k = 0; k < EDGE_IN; k++) { float d = v[k] - mu; var += d * d; }
    var *= (1.f / EDGE_IN);
    float r = rsqrtf(var + 1e-5f);
    float e0 = 0.f, e1 = 0.f;
    #pragma unroll
    for (int k = 0; k < EDGE_IN; k++) {
        float y = (v[k] - mu) * r * g[k] + b[k];
        d_nef[(size_t)ge * EDGE_IN + k] = y;
        e0 += y * d_wae0[k];
        e1 += y * d_wae1[k];
    }
    d_ee0[ge] = e0;
    d_ee1[ge] = e1;
}

// ---------------- single-block exclusive scan of degrees -------------------
__global__ void k_scan()
{
    const int T = 1024, CH = 40;   // 1024*40 >= 40000
    __shared__ int sc[T];
    int t = threadIdx.x;
    int beg = t * CH, end = min(beg + CH, NN);
    int s = 0;
    for (int i = beg; i < end; i++) s += d_off[i];
    sc[t] = s;
    __syncthreads();
    for (int d = 1; d < T; d <<= 1) {
        int v = (t >= d) ? sc[t - d] : 0;
        __syncthreads();
        sc[t] += v;
        __syncthreads();
    }
    int run = (t == 0) ? 0 : sc[t - 1];
    for (int i = beg; i < end; i++) {
        int v = d_off[i];
        d_off[i] = run;
        d_cur[i] = run;
        run += v;
    }
    if (t == T - 1) d_off[NN] = sc[T - 1];
}

// ---------------- scatter edges into CSR ------------------------------------
__global__ void k_scatter(const int* __restrict__ ei)
{
    int ge = blockIdx.x * 256 + threadIdx.x;
    if (ge >= GE) return;
    int bb = ge / EPG;
    int e  = ge - bb * EPG;
    int dst = ei[EPG + e] + bb * NPG;
    int pos = atomicAdd(&d_cur[dst], 1);
    d_csr[pos] = ge;
}

// -------- node projection body: h = in@W, s_src = h.asrc, s_dst = h.adst ----
template<int IN, int OUT>
__device__ __forceinline__ void proj_body(const float* __restrict__ in,
                                          const float* __restrict__ W,
                                          const float* __restrict__ asrc,
                                          const float* __restrict__ adst,
                                          float* __restrict__ h,
                                          float* __restrict__ ss,
                                          float* __restrict__ sd)
{
    constexpr int NPB = 256 / OUT;
    __shared__ float sin_[NPB * IN];
    __shared__ float red[256];
    int t = threadIdx.x;
    int gidx = t / OUT, c = t % OUT;
    int n0 = blockIdx.x * NPB;
    for (int i = t; i < NPB * IN; i += 256) {
        int node = n0 + i / IN;
        sin_[i] = (node < NN) ? in[(size_t)node * IN + (i % IN)] : 0.f;
    }
    __syncthreads();
    int n = n0 + gidx;
    float acc = 0.f;
    const float* row = &sin_[gidx * IN];
    for (int k = 0; k < IN; k++) acc += row[k] * W[k * OUT + c];
    if (n < NN) h[(size_t)n * OUT + c] = acc;

    red[t] = acc * asrc[c];
    __syncthreads();
    for (int s = OUT / 2; s > 0; s >>= 1) {
        if (c < s) red[t] += red[t + s];
        __syncthreads();
    }
    if (c == 0 && n < NN) ss[n] = red[t];
    __syncthreads();
    red[t] = acc * adst[c];
    __syncthreads();
    for (int s = OUT / 2; s > 0; s >>= 1) {
        if (c < s) red[t] += red[t + s];
        __syncthreads();
    }
    if (c == 0 && n < NN) sd[n] = red[t];
}

__global__ void k_proj0(const float* __restrict__ W, const float* __restrict__ asrc,
                        const float* __restrict__ adst)
{
    proj_body<NODE_IN, HID>(d_nx, W, asrc, adst, d_h0, d_s0s, d_s0d);
}
__global__ void k_proj1(const float* __restrict__ W, const float* __restrict__ asrc,
                        const float* __restrict__ adst)
{
    proj_body<HID, EMB>(d_g0, W, asrc, adst, d_h1, d_s1s, d_s1d);
}

// -------- GAT aggregation body: warp per dst node, online softmax ----------
template<int OUT, bool DOELU>
__device__ __forceinline__ void agg_body(const float* __restrict__ h,
                                         const float* __restrict__ ss,
                                         const float* __restrict__ sd,
                                         const float* __restrict__ ee,
                                         const float* __restrict__ bias,
                                         float* __restrict__ out)
{
    int warp = threadIdx.x >> 5, lane = threadIdx.x & 31;
    int n = blockIdx.x * 8 + warp;
    if (n >= NN) return;
    int beg = d_off[n], end = d_off[n + 1], deg = end - beg;
    constexpr int K = OUT / 32;
    float acc[K];
    #pragma unroll
    for (int u = 0; u < K; u++) acc[u] = 0.f;

    if (deg > 0) {
        float sdv = sd[n];
        float m = -1e30f, ssum = 0.f;
        for (int i = lane; i < deg; i += 32) {
            int ge = d_csr[beg + i];
            float lg = ss[d_gsrc[ge]] + sdv + ee[ge];
            lg = lg > 0.f ? lg : 0.2f * lg;
            float nm = fmaxf(m, lg);
            ssum = ssum * expf(m - nm) + expf(lg - nm);
            m = nm;
        }
        float M = m;
        #pragma unroll
        for (int o = 16; o; o >>= 1) M = fmaxf(M, __shfl_xor_sync(~0u, M, o));
        ssum *= expf(m - M);
        #pragma unroll
        for (int o = 16; o; o >>= 1) ssum += __shfl_xor_sync(~0u, ssum, o);
        float inv = 1.f / (ssum + 1e-16f);

        for (int base = 0; base < deg; base += 32) {
            int i = base + lane;
            float alpha = 0.f;
            int src = 0;
            if (i < deg) {
                int ge = d_csr[beg + i];
                src = d_gsrc[ge];
                float lg = ss[src] + sdv + ee[ge];
                lg = lg > 0.f ? lg : 0.2f * lg;
                alpha = expf(lg - M) * inv;
            }
            int cnt = min(32, deg - base);
            for (int j = 0; j < cnt; j++) {
                float a = __shfl_sync(~0u, alpha, j);
                int s   = __shfl_sync(~0u, src, j);
                const float* hp = h + (size_t)s * OUT + lane * K;
                if (K == 4) {
                    float4 v = *(const float4*)hp;
                    acc[0] += a * v.x; acc[1] += a * v.y;
                    acc[2] += a * v.z; acc[3] += a * v.w;
                } else {
                    float2 v = *(const float2*)hp;
                    acc[0] += a * v.x; acc[1] += a * v.y;
                }
            }
        }
    }
    #pragma unroll
    for (int u = 0; u < K; u++) {
        float v = acc[u] + bias[lane * K + u];
        if (DOELU) v = v > 0.f ? v : expm1f(v);
        out[(size_t)n * OUT + lane * K + u] = v;
    }
}

__global__ void k_agg0(const float* __restrict__ bias)
{
    agg_body<HID, true>(d_h0, d_s0s, d_s0d, d_ee0, bias, d_g0);
}
__global__ void k_agg1(const float* __restrict__ bias)
{
    agg_body<EMB, false>(d_h1, d_s1s, d_s1d, d_ee1, bias, d_emb);
}

// ------ pooling per graph (mean+max) then D = ctx @ W1[144:272] + b1 --------
__global__ void k_pool(const float* __restrict__ W1, const float* __restrict__ b1)
{
    int b = blockIdx.x;
    int t = threadIdx.x;                 // 1024
    int c = t & 63, r = t >> 6;          // 16 rows x 64 channels
    float sm = 0.f, mx = -1e30f;
    for (int n = r; n < NPG; n += 16) {
        float v = d_emb[((size_t)(b * NPG + n)) * EMB + c];
        sm += v;
        mx = fmaxf(mx, v);
    }
    __shared__ float sS[16][64], sM[16][64];
    __shared__ float ctx[128];
    sS[r][c] = sm; sM[r][c] = mx;
    __syncthreads();
    if (r == 0) {
        float s = 0.f, m = -1e30f;
        #pragma unroll
        for (int i = 0; i < 16; i++) { s += sS[i][c]; m = fmaxf(m, sM[i][c]); }
        ctx[c] = s * (1.f / NPG);
        ctx[64 + c] = m;
    }
    __syncthreads();
    if (t < 128) {
        float acc = b1[t];
        for (int k = 0; k < 128; k++) acc += ctx[k] * W1[(144 + k) * 128 + t];
        d_D[b * 128 + t] = acc;
    }
}

// ------ per-node A = emb@W1[0:64], B = emb@W1[64:128] ----------------------
__global__ void k_AB(const float* __restrict__ W1)
{
    int n = blockIdx.x;
    int t = threadIdx.x;
    __shared__ float se[EMB];
    if (t < EMB) se[t] = d_emb[(size_t)n * EMB + t];
    __syncthreads();
    if (t < 128) {
        float acc = 0.f;
        for (int k = 0; k < EMB; k++) acc += se[k] * W1[k * 128 + t];
        d_A[(size_t)n * 128 + t] = acc;
    } else {
        int j = t - 128;
        float acc = 0.f;
        for (int k = 0; k < EMB; k++) acc += se[k] * W1[(EMB + k) * 128 + j];
        d_Bm[(size_t)n * 128 + j] = acc;
    }
}

// ------ final fused edge MLP: warp per edge ---------------------------------
__global__ void k_final(const int* __restrict__ ei, const float* __restrict__ W1,
                        const float* __restrict__ W2, const float* __restrict__ b2,
                        float* __restrict__ out)
{
    __shared__ __align__(16) float sW[16 * 128];
    __shared__ float sV[128];
    int t = threadIdx.x;
    for (int i = t; i < 16 * 128; i += 256)
        sW[i] = W1[(128 + (i >> 7)) * 128 + (i & 127)];
    if (t < 128) sV[t] = W2[t];
    __syncthreads();

    int warp = t >> 5, lane = t & 31;
    int ge = blockIdx.x * 8 + warp;
    if (ge >= GE) return;
    int bb = ge / EPG;
    int e  = ge - bb * EPG;
    int src = d_gsrc[ge];
    int dst = ei[EPG + e] + bb * NPG;

    float efv = lane < 16 ? d_nef[(size_t)ge * 16 + lane] : 0.f;
    int j0 = lane * 4;
    float4 va = *(const float4*)(d_A  + (size_t)src * 128 + j0);
    float4 vb = *(const float4*)(d_Bm + (size_t)dst * 128 + j0);
    float4 vd = *(const float4*)(d_D  + bb * 128 + j0);
    float4 v;
    v.x = va.x + vb.x + vd.x;
    v.y = va.y + vb.y + vd.y;
    v.z = va.z + vb.z + vd.z;
    v.w = va.w + vb.w + vd.w;
    #pragma unroll
    for (int k = 0; k < 16; k++) {
        float ek = __shfl_sync(~0u, efv, k);
        float4 w = *(const float4*)(sW + k * 128 + j0);
        v.x += ek * w.x; v.y += ek * w.y; v.z += ek * w.z; v.w += ek * w.w;
    }
    float p = fmaxf(v.x, 0.f) * sV[j0]     + fmaxf(v.y, 0.f) * sV[j0 + 1]
            + fmaxf(v.z, 0.f) * sV[j0 + 2] + fmaxf(v.w, 0.f) * sV[j0 + 3];
    #pragma unroll
    for (int o = 16; o; o >>= 1) p += __shfl_xor_sync(~0u, p, o);
    if (lane == 0) out[ge] = p + b2[0];
}

// ---------------------------------------------------------------------------
extern "C" void kernel_launch(void* const* d_in, const int* in_sizes, int n_in,
                              void* d_out, int out_size)
{
    const float* node_x    = (const float*)d_in[0];
    const float* edge_attr = (const float*)d_in[1];
    const int*   edge_idx  = (const int*)  d_in[2];
    const float* ln_ng     = (const float*)d_in[3];
    const float* ln_nb     = (const float*)d_in[4];
    const float* ln_eg     = (const float*)d_in[5];
    const float* ln_eb     = (const float*)d_in[6];
    const float* g0_W      = (const float*)d_in[7];
    const float* g0_We     = (const float*)d_in[8];
    const float* g0_asrc   = (const float*)d_in[9];
    const float* g0_adst   = (const float*)d_in[10];
    const float* g0_ae     = (const float*)d_in[11];
    const float* g0_b      = (const float*)d_in[12];
    const float* g1_W      = (const float*)d_in[13];
    const float* g1_We     = (const float*)d_in[14];
    const float* g1_asrc   = (const float*)d_in[15];
    const float* g1_adst   = (const float*)d_in[16];
    const float* g1_ae     = (const float*)d_in[17];
    const float* g1_b      = (const float*)d_in[18];
    const float* mlp_W1    = (const float*)d_in[19];
    const float* mlp_b1    = (const float*)d_in[20];
    const float* mlp_W2    = (const float*)d_in[21];
    const float* mlp_b2    = (const float*)d_in[22];
    float* out = (float*)d_out;

    k_pre<<<160, 256>>>(g0_We, g0_ae, g1_We, g1_ae);
    k_ln_node<<<NN / 8, 256>>>(node_x, ln_ng, ln_nb);
    k_ln_edge<<<GE / 256, 256>>>(edge_attr, ln_eg, ln_eb, edge_idx);
    k_scan<<<1, 1024>>>();
    k_scatter<<<GE / 256, 256>>>(edge_idx);

    k_proj0<<<NN / 2, 256>>>(g0_W, g0_asrc, g0_adst);
    k_agg0<<<NN / 8, 256>>>(g0_b);
    k_proj1<<<NN / 4, 256>>>(g1_W, g1_asrc, g1_adst);
    k_agg1<<<NN / 8, 256>>>(g1_b);

    k_pool<<<BB, 1024>>>(mlp_W1, mlp_b1);
    k_AB<<<NN, 256>>>(mlp_W1);
    k_final<<<GE / 8, 256>>>(edge_idx, mlp_W1, mlp_W2, mlp_b2, out);
}

// round 3
// speedup vs baseline: 1.1291x; 1.1291x over previous
#include <cuda_runtime.h>
#include <math.h>

#define BB    8
#define NPG   5000      // nodes per graph
#define EPG   80000     // edges per graph
#define NN    40000     // B*N
#define GE    640000    // B*E
#define NODE_IN 32
#define EDGE_IN 16
#define HID   128
#define EMB   64

// ---------------- scratch (static device arrays; no allocation) -------------
__device__ float d_nx[NN * NODE_IN];
__device__ float d_nef[GE * EDGE_IN];
__device__ float d_ee0[GE];
__device__ float d_ee1[GE];
__device__ int   d_gsrc[GE];
__device__ int   d_cnt[NN];                 // per-node degree (atomic count)
__device__ int   d_beg[NN];                 // segment base per node
__device__ int   d_cur[NN];                 // scatter cursors
__device__ int   d_csr[GE];                 // edge ids grouped by dst
__device__ int   d_ctr;                     // global segment allocator
__device__ float d_h0[NN * HID];
__device__ float d_s0s[NN], d_s0d[NN];
__device__ float d_g0[NN * HID];
__device__ float d_h1[NN * EMB];
__device__ float d_s1s[NN], d_s1d[NN];
__device__ float d_emb[NN * EMB];
__device__ float d_A[NN * HID];
__device__ float d_Bm[NN * HID];
__device__ float d_D[BB * HID];
__device__ float d_wae0[EDGE_IN], d_wae1[EDGE_IN];

// ---------------- k_pre: zero counters + compute wae vectors ---------------
__global__ void k_pre(const float* __restrict__ We0, const float* __restrict__ ae0,
                      const float* __restrict__ We1, const float* __restrict__ ae1)
{
    int t = blockIdx.x * blockDim.x + threadIdx.x;
    for (int i = t; i < NN; i += gridDim.x * blockDim.x) d_cnt[i] = 0;
    if (t == 0) d_ctr = 0;
    if (blockIdx.x == 0) {
        int tt = threadIdx.x;
        if (tt < EDGE_IN) {
            float s = 0.f;
            for (int c = 0; c < HID; c++) s += We0[tt * HID + c] * ae0[c];
            d_wae0[tt] = s;
        } else if (tt < 2 * EDGE_IN) {
            int k = tt - EDGE_IN;
            float s = 0.f;
            for (int c = 0; c < EMB; c++) s += We1[k * EMB + c] * ae1[c];
            d_wae1[k] = s;
        }
    }
}

// ---------------- node layernorm: warp per node (32 channels) --------------
__global__ void k_ln_node(const float* __restrict__ x, const float* __restrict__ g,
                          const float* __restrict__ b)
{
    int warp = threadIdx.x >> 5, lane = threadIdx.x & 31;
    int n = blockIdx.x * 8 + warp;
    if (n >= NN) return;
    float v = x[n * 32 + lane];
    float mu = v;
    #pragma unroll
    for (int o = 16; o; o >>= 1) mu += __shfl_xor_sync(~0u, mu, o);
    mu *= (1.f / 32.f);
    float d = v - mu;
    float var = d * d;
    #pragma unroll
    for (int o = 16; o; o >>= 1) var += __shfl_xor_sync(~0u, var, o);
    var *= (1.f / 32.f);
    d_nx[n * 32 + lane] = d * rsqrtf(var + 1e-5f) * g[lane] + b[lane];
}

// ------------- edge layernorm + logit terms + gsrc + degree count ----------
__global__ void k_ln_edge(const float* __restrict__ ea, const float* __restrict__ g,
                          const float* __restrict__ b, const int* __restrict__ ei)
{
    int ge = blockIdx.x * 256 + threadIdx.x;
    if (ge >= GE) return;
    int bb = ge / EPG;
    int e  = ge - bb * EPG;
    int src = ei[e] + bb * NPG;
    int dst = ei[EPG + e] + bb * NPG;
    d_gsrc[ge] = src;
    atomicAdd(&d_cnt[dst], 1);

    const float* row = ea + (size_t)ge * EDGE_IN;
    float v[EDGE_IN];
    float mu = 0.f;
    #pragma unroll
    for (int k = 0; k < EDGE_IN; k++) { v[k] = row[k]; mu += v[k]; }
    mu *= (1.f / EDGE_IN);
    float var = 0.f;
    #pragma unroll
    for (int k = 0; k < EDGE_IN; k++) { float d = v[k] - mu; var += d * d; }
    var *= (1.f / EDGE_IN);
    float r = rsqrtf(var + 1e-5f);
    float e0 = 0.f, e1 = 0.f;
    #pragma unroll
    for (int k = 0; k < EDGE_IN; k++) {
        float y = (v[k] - mu) * r * g[k] + b[k];
        d_nef[(size_t)ge * EDGE_IN + k] = y;
        e0 += y * d_wae0[k];
        e1 += y * d_wae1[k];
    }
    d_ee0[ge] = e0;
    d_ee1[ge] = e1;
}

// -------- segment assignment: order-free replacement for prefix scan --------
__global__ void k_assign()
{
    int n = blockIdx.x * 256 + threadIdx.x;
    if (n >= NN) return;
    int deg = d_cnt[n];
    int beg = atomicAdd(&d_ctr, deg);
    d_beg[n] = beg;
    d_cur[n] = beg;
}

// ---------------- scatter edges into CSR ------------------------------------
__global__ void k_scatter(const int* __restrict__ ei)
{
    int ge = blockIdx.x * 256 + threadIdx.x;
    if (ge >= GE) return;
    int bb = ge / EPG;
    int e  = ge - bb * EPG;
    int dst = ei[EPG + e] + bb * NPG;
    int pos = atomicAdd(&d_cur[dst], 1);
    d_csr[pos] = ge;
}

// -------- node projection body: h = in@W, s_src = h.asrc, s_dst = h.adst ----
template<int IN, int OUT>
__device__ __forceinline__ void proj_body(const float* __restrict__ in,
                                          const float* __restrict__ W,
                                          const float* __restrict__ asrc,
                                          const float* __restrict__ adst,
                                          float* __restrict__ h,
                                          float* __restrict__ ss,
                                          float* __restrict__ sd)
{
    constexpr int NPB = 256 / OUT;
    __shared__ float sin_[NPB * IN];
    __shared__ float red[256];
    int t = threadIdx.x;
    int gidx = t / OUT, c = t % OUT;
    int n0 = blockIdx.x * NPB;
    for (int i = t; i < NPB * IN; i += 256) {
        int node = n0 + i / IN;
        sin_[i] = (node < NN) ? in[(size_t)node * IN + (i % IN)] : 0.f;
    }
    __syncthreads();
    int n = n0 + gidx;
    float acc = 0.f;
    const float* row = &sin_[gidx * IN];
    for (int k = 0; k < IN; k++) acc += row[k] * W[k * OUT + c];
    if (n < NN) h[(size_t)n * OUT + c] = acc;

    red[t] = acc * asrc[c];
    __syncthreads();
    for (int s = OUT / 2; s > 0; s >>= 1) {
        if (c < s) red[t] += red[t + s];
        __syncthreads();
    }
    if (c == 0 && n < NN) ss[n] = red[t];
    __syncthreads();
    red[t] = acc * adst[c];
    __syncthreads();
    for (int s = OUT / 2; s > 0; s >>= 1) {
        if (c < s) red[t] += red[t + s];
        __syncthreads();
    }
    if (c == 0 && n < NN) sd[n] = red[t];
}

__global__ void k_proj0(const float* __restrict__ W, const float* __restrict__ asrc,
                        const float* __restrict__ adst)
{
    proj_body<NODE_IN, HID>(d_nx, W, asrc, adst, d_h0, d_s0s, d_s0d);
}
__global__ void k_proj1(const float* __restrict__ W, const float* __restrict__ asrc,
                        const float* __restrict__ adst)
{
    proj_body<HID, EMB>(d_g0, W, asrc, adst, d_h1, d_s1s, d_s1d);
}

// -------- GAT aggregation body: warp per dst node, online softmax ----------
template<int OUT, bool DOELU>
__device__ __forceinline__ void agg_body(const float* __restrict__ h,
                                         const float* __restrict__ ss,
                                         const float* __restrict__ sd,
                                         const float* __restrict__ ee,
                                         const float* __restrict__ bias,
                                         float* __restrict__ out)
{
    int warp = threadIdx.x >> 5, lane = threadIdx.x & 31;
    int n = blockIdx.x * 8 + warp;
    if (n >= NN) return;
    int beg = d_beg[n], deg = d_cnt[n];
    constexpr int K = OUT / 32;
    float acc[K];
    #pragma unroll
    for (int u = 0; u < K; u++) acc[u] = 0.f;

    if (deg > 0) {
        float sdv = sd[n];
        float m = -1e30f, ssum = 0.f;
        for (int i = lane; i < deg; i += 32) {
            int ge = d_csr[beg + i];
            float lg = ss[d_gsrc[ge]] + sdv + ee[ge];
            lg = lg > 0.f ? lg : 0.2f * lg;
            float nm = fmaxf(m, lg);
            ssum = ssum * __expf(m - nm) + __expf(lg - nm);
            m = nm;
        }
        float M = m;
        #pragma unroll
        for (int o = 16; o; o >>= 1) M = fmaxf(M, __shfl_xor_sync(~0u, M, o));
        ssum *= __expf(m - M);
        #pragma unroll
        for (int o = 16; o; o >>= 1) ssum += __shfl_xor_sync(~0u, ssum, o);
        float inv = 1.f / (ssum + 1e-16f);

        for (int base = 0; base < deg; base += 32) {
            int i = base + lane;
            float alpha = 0.f;
            int src = 0;
            if (i < deg) {
                int ge = d_csr[beg + i];
                src = d_gsrc[ge];
                float lg = ss[src] + sdv + ee[ge];
                lg = lg > 0.f ? lg : 0.2f * lg;
                alpha = __expf(lg - M) * inv;
            }
            int cnt = min(32, deg - base);
            for (int j = 0; j < cnt; j++) {
                float a = __shfl_sync(~0u, alpha, j);
                int s   = __shfl_sync(~0u, src, j);
                const float* hp = h + (size_t)s * OUT + lane * K;
                if (K == 4) {
                    float4 v = *(const float4*)hp;
                    acc[0] += a * v.x; acc[1] += a * v.y;
                    acc[2] += a * v.z; acc[3] += a * v.w;
                } else {
                    float2 v = *(const float2*)hp;
                    acc[0] += a * v.x; acc[1] += a * v.y;
                }
            }
        }
    }
    #pragma unroll
    for (int u = 0; u < K; u++) {
        float v = acc[u] + bias[lane * K + u];
        if (DOELU) v = v > 0.f ? v : expm1f(v);
        out[(size_t)n * OUT + lane * K + u] = v;
    }
}

__global__ void k_agg0(const float* __restrict__ bias)
{
    agg_body<HID, true>(d_h0, d_s0s, d_s0d, d_ee0, bias, d_g0);
}
__global__ void k_agg1(const float* __restrict__ bias)
{
    agg_body<EMB, false>(d_h1, d_s1s, d_s1d, d_ee1, bias, d_emb);
}

// ------ pooling per graph (mean+max) then D = ctx @ W1[144:272] + b1 --------
__global__ void k_pool(const float* __restrict__ W1, const float* __restrict__ b1)
{
    int b = blockIdx.x;
    int t = threadIdx.x;                 // 1024
    int c = t & 63, r = t >> 6;          // 16 rows x 64 channels
    float sm = 0.f, mx = -1e30f;
    for (int n = r; n < NPG; n += 16) {
        float v = d_emb[((size_t)(b * NPG + n)) * EMB + c];
        sm += v;
        mx = fmaxf(mx, v);
    }
    __shared__ float sS[16][64], sM[16][64];
    __shared__ float ctx[128];
    sS[r][c] = sm; sM[r][c] = mx;
    __syncthreads();
    if (r == 0) {
        float s = 0.f, m = -1e30f;
        #pragma unroll
        for (int i = 0; i < 16; i++) { s += sS[i][c]; m = fmaxf(m, sM[i][c]); }
        ctx[c] = s * (1.f / NPG);
        ctx[64 + c] = m;
    }
    __syncthreads();
    if (t < 128) {
        float acc = b1[t];
        for (int k = 0; k < 128; k++) acc += ctx[k] * W1[(144 + k) * 128 + t];
        d_D[b * 128 + t] = acc;
    }
}

// ------ per-node A = emb@W1[0:64], B = emb@W1[64:128]: warp per node --------
__global__ void k_AB(const float* __restrict__ W1)
{
    int warp = (blockIdx.x * blockDim.x + threadIdx.x) >> 5;
    int lane = threadIdx.x & 31;
    int nwarps = (gridDim.x * blockDim.x) >> 5;
    for (int n = warp; n < NN; n += nwarps) {
        float e0 = d_emb[(size_t)n * EMB + lane];
        float e1 = d_emb[(size_t)n * EMB + 32 + lane];
        float a0 = 0.f, a1 = 0.f, a2 = 0.f, a3 = 0.f;
        float b0 = 0.f, b1 = 0.f, b2 = 0.f, b3 = 0.f;
        #pragma unroll 4
        for (int k = 0; k < 64; k++) {
            float ev = __shfl_sync(~0u, (k < 32) ? e0 : e1, k & 31);
            const float* wa = W1 + k * 128;
            const float* wb = W1 + (64 + k) * 128;
            a0 += ev * wa[lane];       a1 += ev * wa[lane + 32];
            a2 += ev * wa[lane + 64];  a3 += ev * wa[lane + 96];
            b0 += ev * wb[lane];       b1 += ev * wb[lane + 32];
            b2 += ev * wb[lane + 64];  b3 += ev * wb[lane + 96];
        }
        float* pa = d_A + (size_t)n * 128;
        float* pb = d_Bm + (size_t)n * 128;
        pa[lane] = a0; pa[lane + 32] = a1; pa[lane + 64] = a2; pa[lane + 96] = a3;
        pb[lane] = b0; pb[lane + 32] = b1; pb[lane + 64] = b2; pb[lane + 96] = b3;
    }
}

// ------ final fused edge MLP: persistent, warp per edge ---------------------
__global__ void k_final(const int* __restrict__ ei, const float* __restrict__ W1,
                        const float* __restrict__ W2, const float* __restrict__ b2,
                        float* __restrict__ out)
{
    __shared__ __align__(16) float sW[16 * 128];
    __shared__ float sV[128];
    int t = threadIdx.x;
    for (int i = t; i < 16 * 128; i += 256)
        sW[i] = W1[(128 + (i >> 7)) * 128 + (i & 127)];
    if (t < 128) sV[t] = W2[t];
    __syncthreads();

    int warp = t >> 5, lane = t & 31;
    int j0 = lane * 4;
    float w2x = sV[j0], w2y = sV[j0 + 1], w2z = sV[j0 + 2], w2w = sV[j0 + 3];
    float bias2 = b2[0];

    for (int ge = blockIdx.x * 8 + warp; ge < GE; ge += gridDim.x * 8) {
        int bb = ge / EPG;
        int e  = ge - bb * EPG;
        int src = d_gsrc[ge];
        int dst = ei[EPG + e] + bb * NPG;

        float efv = lane < 16 ? d_nef[(size_t)ge * 16 + lane] : 0.f;
        float4 va = *(const float4*)(d_A  + (size_t)src * 128 + j0);
        float4 vb = *(const float4*)(d_Bm + (size_t)dst * 128 + j0);
        float4 vd = *(const float4*)(d_D  + bb * 128 + j0);
        float4 v;
        v.x = va.x + vb.x + vd.x;
        v.y = va.y + vb.y + vd.y;
        v.z = va.z + vb.z + vd.z;
        v.w = va.w + vb.w + vd.w;
        #pragma unroll
        for (int k = 0; k < 16; k++) {
            float ek = __shfl_sync(~0u, efv, k);
            float4 w = *(const float4*)(sW + k * 128 + j0);
            v.x += ek * w.x; v.y += ek * w.y; v.z += ek * w.z; v.w += ek * w.w;
        }
        float p = fmaxf(v.x, 0.f) * w2x + fmaxf(v.y, 0.f) * w2y
                + fmaxf(v.z, 0.f) * w2z + fmaxf(v.w, 0.f) * w2w;
        #pragma unroll
        for (int o = 16; o; o >>= 1) p += __shfl_xor_sync(~0u, p, o);
        if (lane == 0) out[ge] = p + bias2;
    }
}

// ---------------------------------------------------------------------------
extern "C" void kernel_launch(void* const* d_in, const int* in_sizes, int n_in,
                              void* d_out, int out_size)
{
    const float* node_x    = (const float*)d_in[0];
    const float* edge_attr = (const float*)d_in[1];
    const int*   edge_idx  = (const int*)  d_in[2];
    const float* ln_ng     = (const float*)d_in[3];
    const float* ln_nb     = (const float*)d_in[4];
    const float* ln_eg     = (const float*)d_in[5];
    const float* ln_eb     = (const float*)d_in[6];
    const float* g0_W      = (const float*)d_in[7];
    const float* g0_We     = (const float*)d_in[8];
    const float* g0_asrc   = (const float*)d_in[9];
    const float* g0_adst   = (const float*)d_in[10];
    const float* g0_ae     = (const float*)d_in[11];
    const float* g0_b      = (const float*)d_in[12];
    const float* g1_W      = (const float*)d_in[13];
    const float* g1_We     = (const float*)d_in[14];
    const float* g1_asrc   = (const float*)d_in[15];
    const float* g1_adst   = (const float*)d_in[16];
    const float* g1_ae     = (const float*)d_in[17];
    const float* g1_b      = (const float*)d_in[18];
    const float* mlp_W1    = (const float*)d_in[19];
    const float* mlp_b1    = (const float*)d_in[20];
    const float* mlp_W2    = (const float*)d_in[21];
    const float* mlp_b2    = (const float*)d_in[22];
    float* out = (float*)d_out;

    k_pre<<<160, 256>>>(g0_We, g0_ae, g1_We, g1_ae);
    k_ln_node<<<NN / 8, 256>>>(node_x, ln_ng, ln_nb);
    k_ln_edge<<<GE / 256, 256>>>(edge_attr, ln_eg, ln_eb, edge_idx);
    k_assign<<<(NN + 255) / 256, 256>>>();
    k_scatter<<<GE / 256, 256>>>(edge_idx);

    k_proj0<<<NN / 2, 256>>>(g0_W, g0_asrc, g0_adst);
    k_agg0<<<NN / 8, 256>>>(g0_b);
    k_proj1<<<NN / 4, 256>>>(g1_W, g1_asrc, g1_adst);
    k_agg1<<<NN / 8, 256>>>(g1_b);

    k_pool<<<BB, 1024>>>(mlp_W1, mlp_b1);
    k_AB<<<1184, 256>>>(mlp_W1);
    k_final<<<1184, 256>>>(edge_idx, mlp_W1, mlp_W2, mlp_b2, out);
}

// round 4
// speedup vs baseline: 1.6310x; 1.4446x over previous
#include <cuda_runtime.h>
#include <math.h>

#define BB    8
#define NPG   5000
#define EPG   80000
#define NN    40000
#define GE    640000
#define HID   128
#define EMB   64

// ---------------- scratch (static device arrays) ---------------------------
__device__ float d_nx[NN * 32];
__device__ float d_nef[GE * 16];
__device__ float d_ee0[GE], d_ee1[GE];
__device__ int   d_gsrc[GE];
__device__ int   d_cnt[NN], d_beg[NN], d_cur[NN], d_csr[GE];
__device__ int   d_ctr;
__device__ float d_h0[NN * HID];
__device__ float d_s0s[NN], d_s0d[NN];
__device__ float d_g0[NN * HID];
__device__ float d_h1[NN * EMB];
__device__ float d_s1s[NN], d_s1d[NN];
__device__ float d_emb[NN * EMB];
__device__ float d_A[NN * HID], d_Bm[NN * HID], d_D[BB * HID];
__device__ float d_wae0[16], d_wae1[16];
__device__ float d_was0[32], d_wad0[32];
__device__ float d_was1[128], d_wad1[128];
__device__ float d_psum[BB * 8 * 64];     // per-slab partial sums
__device__ unsigned d_pmax[BB * 64];      // encoded float max

__device__ __forceinline__ unsigned encf(float f) {
    unsigned u = __float_as_uint(f);
    return (u & 0x80000000u) ? ~u : (u | 0x80000000u);
}
__device__ __forceinline__ float decf(unsigned e) {
    return (e & 0x80000000u) ? __uint_as_float(e ^ 0x80000000u) : __uint_as_float(~e);
}

// ------------- k_pre: zero counters + precompute folded weight vectors ------
__global__ void k_pre(const float* __restrict__ We0, const float* __restrict__ ae0,
                      const float* __restrict__ We1, const float* __restrict__ ae1,
                      const float* __restrict__ W0,  const float* __restrict__ as0,
                      const float* __restrict__ ad0, const float* __restrict__ W1g,
                      const float* __restrict__ as1, const float* __restrict__ ad1)
{
    int t = blockIdx.x * blockDim.x + threadIdx.x;
    int stride = gridDim.x * blockDim.x;
    for (int i = t; i < NN; i += stride) d_cnt[i] = 0;
    for (int i = t; i < BB * 64; i += stride) d_pmax[i] = encf(-1e30f);
    if (t == 0) d_ctr = 0;
    if (blockIdx.x == 0) {
        int tt = threadIdx.x;
        if (tt < 16) {
            float s = 0.f;
            for (int c = 0; c < 128; c++) s += We0[tt * 128 + c] * ae0[c];
            d_wae0[tt] = s;
        } else if (tt < 32) {
            int k = tt - 16;
            float s = 0.f;
            for (int c = 0; c < 64; c++) s += We1[k * 64 + c] * ae1[c];
            d_wae1[k] = s;
        } else if (tt < 64) {
            int k = tt - 32;
            float s0 = 0.f, s1 = 0.f;
            for (int c = 0; c < 128; c++) {
                float w = W0[k * 128 + c];
                s0 += w * as0[c]; s1 += w * ad0[c];
            }
            d_was0[k] = s0; d_wad0[k] = s1;
        }
    } else if (blockIdx.x == 1) {
        int tt = threadIdx.x;
        if (tt < 128) {
            float s0 = 0.f, s1 = 0.f;
            for (int c = 0; c < 64; c++) {
                float w = W1g[tt * 64 + c];
                s0 += w * as1[c]; s1 += w * ad1[c];
            }
            d_was1[tt] = s0; d_wad1[tt] = s1;
        }
    }
}

// ------------- node layernorm + folded s0s/s0d: warp per node ---------------
__global__ void k_ln_node(const float* __restrict__ x, const float* __restrict__ g,
                          const float* __restrict__ b)
{
    int warp = threadIdx.x >> 5, lane = threadIdx.x & 31;
    int n = blockIdx.x * 8 + warp;
    if (n >= NN) return;
    float v = x[n * 32 + lane];
    float mu = v;
    #pragma unroll
    for (int o = 16; o; o >>= 1) mu += __shfl_xor_sync(~0u, mu, o);
    mu *= (1.f / 32.f);
    float d = v - mu;
    float var = d * d;
    #pragma unroll
    for (int o = 16; o; o >>= 1) var += __shfl_xor_sync(~0u, var, o);
    var *= (1.f / 32.f);
    float y = d * rsqrtf(var + 1e-5f) * g[lane] + b[lane];
    d_nx[n * 32 + lane] = y;
    float ps = y * d_was0[lane], pd = y * d_wad0[lane];
    #pragma unroll
    for (int o = 16; o; o >>= 1) {
        ps += __shfl_xor_sync(~0u, ps, o);
        pd += __shfl_xor_sync(~0u, pd, o);
    }
    if (lane == 0) { d_s0s[n] = ps; d_s0d[n] = pd; }
}

// ------- edge layernorm (float4) + logit terms + gsrc + degree count --------
__global__ void k_ln_edge(const float* __restrict__ ea, const float* __restrict__ g,
                          const float* __restrict__ b, const int* __restrict__ ei)
{
    __shared__ float sg[16], sb[16], sw0[16], sw1[16];
    if (threadIdx.x < 16) {
        sg[threadIdx.x] = g[threadIdx.x];
        sb[threadIdx.x] = b[threadIdx.x];
        sw0[threadIdx.x] = d_wae0[threadIdx.x];
        sw1[threadIdx.x] = d_wae1[threadIdx.x];
    }
    __syncthreads();
    int ge = blockIdx.x * 256 + threadIdx.x;
    if (ge >= GE) return;
    int bb = ge / EPG;
    int e  = ge - bb * EPG;
    int src = ei[e] + bb * NPG;
    int dst = ei[EPG + e] + bb * NPG;
    d_gsrc[ge] = src;
    atomicAdd(&d_cnt[dst], 1);

    const float4* rp = (const float4*)(ea + (size_t)ge * 16);
    float4 q[4];
    q[0] = rp[0]; q[1] = rp[1]; q[2] = rp[2]; q[3] = rp[3];
    float* v = (float*)q;
    float mu = 0.f;
    #pragma unroll
    for (int k = 0; k < 16; k++) mu += v[k];
    mu *= (1.f / 16.f);
    float var = 0.f;
    #pragma unroll
    for (int k = 0; k < 16; k++) { float d = v[k] - mu; var += d * d; }
    var *= (1.f / 16.f);
    float r = rsqrtf(var + 1e-5f);
    float e0 = 0.f, e1 = 0.f;
    #pragma unroll
    for (int k = 0; k < 16; k++) {
        float y = (v[k] - mu) * r * sg[k] + sb[k];
        v[k] = y;
        e0 += y * sw0[k];
        e1 += y * sw1[k];
    }
    float4* wp = (float4*)(d_nef + (size_t)ge * 16);
    wp[0] = q[0]; wp[1] = q[1]; wp[2] = q[2]; wp[3] = q[3];
    d_ee0[ge] = e0;
    d_ee1[ge] = e1;
}

// -------- segment assignment (order-free) + scatter --------------------------
__global__ void k_assign()
{
    int n = blockIdx.x * 256 + threadIdx.x;
    if (n >= NN) return;
    int deg = d_cnt[n];
    int beg = atomicAdd(&d_ctr, deg);
    d_beg[n] = beg;
    d_cur[n] = beg;
}

__global__ void k_scatter(const int* __restrict__ ei)
{
    int ge = blockIdx.x * 256 + threadIdx.x;
    if (ge >= GE) return;
    int bb = ge / EPG;
    int e  = ge - bb * EPG;
    int dst = ei[EPG + e] + bb * NPG;
    int pos = atomicAdd(&d_cur[dst], 1);
    d_csr[pos] = ge;
}

// -------- proj0: pure GEMM 40000x32 -> 128, 8 nodes/block --------------------
__global__ void k_proj0(const float* __restrict__ W)
{
    __shared__ float sin_[8 * 32];
    int t = threadIdx.x;
    int n0 = blockIdx.x * 8;
    sin_[t] = d_nx[n0 * 32 + t];
    __syncthreads();
    int c = t & 127, gidx = t >> 7;      // gidx in {0,1}, 4 nodes each
    float a0 = 0.f, a1 = 0.f, a2 = 0.f, a3 = 0.f;
    #pragma unroll
    for (int k = 0; k < 32; k++) {
        float w = W[k * 128 + c];
        a0 += sin_[(gidx * 4 + 0) * 32 + k] * w;
        a1 += sin_[(gidx * 4 + 1) * 32 + k] * w;
        a2 += sin_[(gidx * 4 + 2) * 32 + k] * w;
        a3 += sin_[(gidx * 4 + 3) * 32 + k] * w;
    }
    int nb = n0 + gidx * 4;
    d_h0[(size_t)(nb + 0) * 128 + c] = a0;
    d_h0[(size_t)(nb + 1) * 128 + c] = a1;
    d_h0[(size_t)(nb + 2) * 128 + c] = a2;
    d_h0[(size_t)(nb + 3) * 128 + c] = a3;
}

// -------- proj1: pure GEMM 40000x128 -> 64, 8 nodes/block --------------------
__global__ void k_proj1(const float* __restrict__ W)
{
    __shared__ float sin_[8 * 128];
    int t = threadIdx.x;
    int n0 = blockIdx.x * 8;
    #pragma unroll
    for (int i = t; i < 8 * 128; i += 256) sin_[i] = d_g0[(size_t)n0 * 128 + i];
    __syncthreads();
    int c = t & 63, gidx = t >> 6;       // gidx in {0..3}, 2 nodes each
    float a0 = 0.f, a1 = 0.f;
    #pragma unroll 8
    for (int k = 0; k < 128; k++) {
        float w = W[k * 64 + c];
        a0 += sin_[(gidx * 2 + 0) * 128 + k] * w;
        a1 += sin_[(gidx * 2 + 1) * 128 + k] * w;
    }
    int nb = n0 + gidx * 2;
    d_h1[(size_t)(nb + 0) * 64 + c] = a0;
    d_h1[(size_t)(nb + 1) * 64 + c] = a1;
}

// -------- 4-edge gather helper -----------------------------------------------
template<int K>
__device__ __forceinline__ void gather4(float* acc, const float* __restrict__ h,
                                        int S0, int S1, int S2, int S3,
                                        float A0, float A1, float A2, float A3, int lane)
{
    constexpr int OUT = K * 32;
    const float* p0 = h + (size_t)S0 * OUT + lane * K;
    const float* p1 = h + (size_t)S1 * OUT + lane * K;
    const float* p2 = h + (size_t)S2 * OUT + lane * K;
    const float* p3 = h + (size_t)S3 * OUT + lane * K;
    if constexpr (K == 4) {
        float4 u0 = *(const float4*)p0;
        float4 u1 = *(const float4*)p1;
        float4 u2 = *(const float4*)p2;
        float4 u3 = *(const float4*)p3;
        acc[0] += A0 * u0.x + A1 * u1.x + A2 * u2.x + A3 * u3.x;
        acc[1] += A0 * u0.y + A1 * u1.y + A2 * u2.y + A3 * u3.y;
        acc[2] += A0 * u0.z + A1 * u1.z + A2 * u2.z + A3 * u3.z;
        acc[3] += A0 * u0.w + A1 * u1.w + A2 * u2.w + A3 * u3.w;
    } else {
        float2 u0 = *(const float2*)p0;
        float2 u1 = *(const float2*)p1;
        float2 u2 = *(const float2*)p2;
        float2 u3 = *(const float2*)p3;
        acc[0] += A0 * u0.x + A1 * u1.x + A2 * u2.x + A3 * u3.x;
        acc[1] += A0 * u0.y + A1 * u1.y + A2 * u2.y + A3 * u3.y;
    }
}

// -------- GAT aggregation: warp per dst node ---------------------------------
template<int OUT, bool DOELU, bool DOS1>
__device__ __forceinline__ void agg_body(const float* __restrict__ h,
                                         const float* __restrict__ ss,
                                         const float* __restrict__ sd,
                                         const float* __restrict__ ee,
                                         const float* __restrict__ bias,
                                         float* __restrict__ out)
{
    int warp = threadIdx.x >> 5, lane = threadIdx.x & 31;
    int n = blockIdx.x * 8 + warp;
    if (n >= NN) return;
    int beg = d_beg[n], deg = d_cnt[n];
    constexpr int K = OUT / 32;
    float acc[K];
    #pragma unroll
    for (int u = 0; u < K; u++) acc[u] = 0.f;

    if (deg > 0) {
        float sdv = sd[n];
        if (deg <= 32) {
            // fast path: one edge per lane
            int src = 0;
            float lg = -1e30f;
            if (lane < deg) {
                int ge = d_csr[beg + lane];
                src = d_gsrc[ge];
                lg = ss[src] + sdv + ee[ge];
                lg = lg > 0.f ? lg : 0.2f * lg;
            }
            float M = lg;
            #pragma unroll
            for (int o = 16; o; o >>= 1) M = fmaxf(M, __shfl_xor_sync(~0u, M, o));
            float ex = (lane < deg) ? __expf(lg - M) : 0.f;
            float sm = ex;
            #pragma unroll
            for (int o = 16; o; o >>= 1) sm += __shfl_xor_sync(~0u, sm, o);
            float alpha = ex / (sm + 1e-16f);
            for (int j = 0; j < deg; j += 4) {
                float A0 = __shfl_sync(~0u, alpha, j);
                float A1 = __shfl_sync(~0u, alpha, j + 1);
                float A2 = __shfl_sync(~0u, alpha, j + 2);
                float A3 = __shfl_sync(~0u, alpha, j + 3);
                int S0 = __shfl_sync(~0u, src, j);
                int S1 = __shfl_sync(~0u, src, j + 1);
                int S2 = __shfl_sync(~0u, src, j + 2);
                int S3 = __shfl_sync(~0u, src, j + 3);
                gather4<K>(acc, h, S0, S1, S2, S3, A0, A1, A2, A3, lane);
            }
        } else {
            // general path (rare)
            float m = -1e30f, sm = 0.f;
            for (int i = lane; i < deg; i += 32) {
                int ge = d_csr[beg + i];
                float lg = ss[d_gsrc[ge]] + sdv + ee[ge];
                lg = lg > 0.f ? lg : 0.2f * lg;
                float nm = fmaxf(m, lg);
                sm = sm * __expf(m - nm) + __expf(lg - nm);
                m = nm;
            }
            float M = m;
            #pragma unroll
            for (int o = 16; o; o >>= 1) M = fmaxf(M, __shfl_xor_sync(~0u, M, o));
            sm *= __expf(m - M);
            #pragma unroll
            for (int o = 16; o; o >>= 1) sm += __shfl_xor_sync(~0u, sm, o);
            float inv = 1.f / (sm + 1e-16f);
            for (int base = 0; base < deg; base += 32) {
                int i = base + lane;
                float alpha = 0.f;
                int src = 0;
                if (i < deg) {
                    int ge = d_csr[beg + i];
                    src = d_gsrc[ge];
                    float lg = ss[src] + sdv + ee[ge];
                    lg = lg > 0.f ? lg : 0.2f * lg;
                    alpha = __expf(lg - M) * inv;
                }
                int cnt = min(32, deg - base);
                for (int j = 0; j < cnt; j += 4) {
                    float A0 = __shfl_sync(~0u, alpha, j);
                    float A1 = __shfl_sync(~0u, alpha, j + 1);
                    float A2 = __shfl_sync(~0u, alpha, j + 2);
                    float A3 = __shfl_sync(~0u, alpha, j + 3);
                    int S0 = __shfl_sync(~0u, src, j);
                    int S1 = __shfl_sync(~0u, src, j + 1);
                    int S2 = __shfl_sync(~0u, src, j + 2);
                    int S3 = __shfl_sync(~0u, src, j + 3);
                    gather4<K>(acc, h, S0, S1, S2, S3, A0, A1, A2, A3, lane);
                }
            }
        }
    }
    float v[K];
    #pragma unroll
    for (int u = 0; u < K; u++) {
        v[u] = acc[u] + bias[lane * K + u];
        if (DOELU) v[u] = v[u] > 0.f ? v[u] : expm1f(v[u]);
        out[(size_t)n * OUT + lane * K + u] = v[u];
    }
    if (DOS1) {
        float ps = 0.f, pd = 0.f;
        #pragma unroll
        for (int u = 0; u < K; u++) {
            ps += v[u] * d_was1[lane * K + u];
            pd += v[u] * d_wad1[lane * K + u];
        }
        #pragma unroll
        for (int o = 16; o; o >>= 1) {
            ps += __shfl_xor_sync(~0u, ps, o);
            pd += __shfl_xor_sync(~0u, pd, o);
        }
        if (lane == 0) { d_s1s[n] = ps; d_s1d[n] = pd; }
    }
}

__global__ void k_agg0(const float* __restrict__ bias)
{
    agg_body<HID, true, true>(d_h0, d_s0s, d_s0d, d_ee0, bias, d_g0);
}
__global__ void k_agg1(const float* __restrict__ bias)
{
    agg_body<EMB, false, false>(d_h1, d_s1s, d_s1d, d_ee1, bias, d_emb);
}

// ------ pooling partials: 8 slabs per graph ---------------------------------
__global__ void k_pool_partial()
{
    int b = blockIdx.x >> 3, slab = blockIdx.x & 7;
    int t = threadIdx.x;
    int c = t & 63, r = t >> 6;          // 4 rows x 64 channels
    float sm = 0.f, mx = -1e30f;
    int nb = b * NPG + slab * 625;
    for (int i = r; i < 625; i += 4) {
        float v = d_emb[(size_t)(nb + i) * 64 + c];
        sm += v;
        mx = fmaxf(mx, v);
    }
    __shared__ float sS[4][64], sM[4][64];
    sS[r][c] = sm; sM[r][c] = mx;
    __syncthreads();
    if (r == 0) {
        float s = sS[0][c] + sS[1][c] + sS[2][c] + sS[3][c];
        float m = fmaxf(fmaxf(sS ? sM[0][c] : 0.f, sM[1][c]), fmaxf(sM[2][c], sM[3][c]));
        d_psum[((size_t)b * 8 + slab) * 64 + c] = s;
        atomicMax(&d_pmax[b * 64 + c], encf(m));
    }
}

// ------ D = ctx @ W1[144:272] + b1 ------------------------------------------
__global__ void k_D(const float* __restrict__ W1, const float* __restrict__ b1)
{
    int b = blockIdx.x;
    int t = threadIdx.x;
    __shared__ float ctx[128];
    if (t < 64) {
        float s = 0.f;
        #pragma unroll
        for (int slab = 0; slab < 8; slab++) s += d_psum[((size_t)b * 8 + slab) * 64 + t];
        ctx[t] = s * (1.f / NPG);
        ctx[64 + t] = decf(d_pmax[b * 64 + t]);
    }
    __syncthreads();
    float acc = b1[t];
    for (int k = 0; k < 128; k++) acc += ctx[k] * W1[(144 + k) * 128 + t];
    d_D[b * 128 + t] = acc;
}

// ------ per-node A = emb@W1[0:64], B = emb@W1[64:128]: warp per node --------
__global__ void k_AB(const float* __restrict__ W1)
{
    int warp = (blockIdx.x * blockDim.x + threadIdx.x) >> 5;
    int lane = threadIdx.x & 31;
    int nwarps = (gridDim.x * blockDim.x) >> 5;
    for (int n = warp; n < NN; n += nwarps) {
        float e0 = d_emb[(size_t)n * EMB + lane];
        float e1 = d_emb[(size_t)n * EMB + 32 + lane];
        float a0 = 0.f, a1 = 0.f, a2 = 0.f, a3 = 0.f;
        float b0 = 0.f, b1 = 0.f, b2 = 0.f, b3 = 0.f;
        #pragma unroll 4
        for (int k = 0; k < 64; k++) {
            float ev = __shfl_sync(~0u, (k < 32) ? e0 : e1, k & 31);
            const float* wa = W1 + k * 128;
            const float* wb = W1 + (64 + k) * 128;
            a0 += ev * wa[lane];       a1 += ev * wa[lane + 32];
            a2 += ev * wa[lane + 64];  a3 += ev * wa[lane + 96];
            b0 += ev * wb[lane];       b1 += ev * wb[lane + 32];
            b2 += ev * wb[lane + 64];  b3 += ev * wb[lane + 96];
        }
        float* pa = d_A + (size_t)n * 128;
        float* pb = d_Bm + (size_t)n * 128;
        pa[lane] = a0; pa[lane + 32] = a1; pa[lane + 64] = a2; pa[lane + 96] = a3;
        pb[lane] = b0; pb[lane + 32] = b1; pb[lane + 64] = b2; pb[lane + 96] = b3;
    }
}

// ------ final fused edge MLP: persistent, 2 edges per warp iteration ---------
__global__ void k_final(const int* __restrict__ ei, const float* __restrict__ W1,
                        const float* __restrict__ W2, const float* __restrict__ b2,
                        float* __restrict__ out)
{
    __shared__ __align__(16) float sW[16 * 128];
    __shared__ float sV[128];
    int t = threadIdx.x;
    for (int i = t; i < 16 * 128; i += 256)
        sW[i] = W1[(128 + (i >> 7)) * 128 + (i & 127)];
    if (t < 128) sV[t] = W2[t];
    __syncthreads();

    int warp = t >> 5, lane = t & 31;
    int j0 = lane * 4;
    float w2x = sV[j0], w2y = sV[j0 + 1], w2z = sV[j0 + 2], w2w = sV[j0 + 3];
    float bias2 = b2[0];
    int stride = gridDim.x * 16;

    for (int g0 = blockIdx.x * 16 + warp * 2; g0 < GE; g0 += stride) {
        int g1 = g0 + 1;                 // always valid (GE even, g0 even)
        int bb0 = g0 / EPG, e0 = g0 - bb0 * EPG;
        int bb1 = g1 / EPG, e1 = g1 - bb1 * EPG;
        int src0 = d_gsrc[g0], src1 = d_gsrc[g1];
        int dst0 = ei[EPG + e0] + bb0 * NPG;
        int dst1 = ei[EPG + e1] + bb1 * NPG;

        // lanes 0..15: edge0 ef, lanes 16..31: edge1 ef (contiguous 128B)
        float ef2 = d_nef[(size_t)g0 * 16 + lane];

        float4 va0 = *(const float4*)(d_A  + (size_t)src0 * 128 + j0);
        float4 va1 = *(const float4*)(d_A  + (size_t)src1 * 128 + j0);
        float4 vb0 = *(const float4*)(d_Bm + (size_t)dst0 * 128 + j0);
        float4 vb1 = *(const float4*)(d_Bm + (size_t)dst1 * 128 + j0);
        float4 vd0 = *(const float4*)(d_D  + bb0 * 128 + j0);
        float4 vd1 = *(const float4*)(d_D  + bb1 * 128 + j0);
        float4 v0, v1;
        v0.x = va0.x + vb0.x + vd0.x; v0.y = va0.y + vb0.y + vd0.y;
        v0.z = va0.z + vb0.z + vd0.z; v0.w = va0.w + vb0.w + vd0.w;
        v1.x = va1.x + vb1.x + vd1.x; v1.y = va1.y + vb1.y + vd1.y;
        v1.z = va1.z + vb1.z + vd1.z; v1.w = va1.w + vb1.w + vd1.w;
        #pragma unroll
        for (int k = 0; k < 16; k++) {
            float ek0 = __shfl_sync(~0u, ef2, k);
            float ek1 = __shfl_sync(~0u, ef2, 16 + k);
            float4 w = *(const float4*)(sW + k * 128 + j0);
            v0.x += ek0 * w.x; v0.y += ek0 * w.y; v0.z += ek0 * w.z; v0.w += ek0 * w.w;
            v1.x += ek1 * w.x; v1.y += ek1 * w.y; v1.z += ek1 * w.z; v1.w += ek1 * w.w;
        }
        float p0 = fmaxf(v0.x, 0.f) * w2x + fmaxf(v0.y, 0.f) * w2y
                 + fmaxf(v0.z, 0.f) * w2z + fmaxf(v0.w, 0.f) * w2w;
        float p1 = fmaxf(v1.x, 0.f) * w2x + fmaxf(v1.y, 0.f) * w2y
                 + fmaxf(v1.z, 0.f) * w2z + fmaxf(v1.w, 0.f) * w2w;
        #pragma unroll
        for (int o = 16; o; o >>= 1) {
            p0 += __shfl_xor_sync(~0u, p0, o);
            p1 += __shfl_xor_sync(~0u, p1, o);
        }
        if (lane == 0) {
            float2 r; r.x = p0 + bias2; r.y = p1 + bias2;
            *(float2*)(out + g0) = r;
        }
    }
}

// ---------------------------------------------------------------------------
extern "C" void kernel_launch(void* const* d_in, const int* in_sizes, int n_in,
                              void* d_out, int out_size)
{
    const float* node_x    = (const float*)d_in[0];
    const float* edge_attr = (const float*)d_in[1];
    const int*   edge_idx  = (const int*)  d_in[2];
    const float* ln_ng     = (const float*)d_in[3];
    const float* ln_nb     = (const float*)d_in[4];
    const float* ln_eg     = (const float*)d_in[5];
    const float* ln_eb     = (const float*)d_in[6];
    const float* g0_W      = (const float*)d_in[7];
    const float* g0_We     = (const float*)d_in[8];
    const float* g0_asrc   = (const float*)d_in[9];
    const float* g0_adst   = (const float*)d_in[10];
    const float* g0_ae     = (const float*)d_in[11];
    const float* g0_b      = (const float*)d_in[12];
    const float* g1_W      = (const float*)d_in[13];
    const float* g1_We     = (const float*)d_in[14];
    const float* g1_asrc   = (const float*)d_in[15];
    const float* g1_adst   = (const float*)d_in[16];
    const float* g1_ae     = (const float*)d_in[17];
    const float* g1_b      = (const float*)d_in[18];
    const float* mlp_W1    = (const float*)d_in[19];
    const float* mlp_b1    = (const float*)d_in[20];
    const float* mlp_W2    = (const float*)d_in[21];
    const float* mlp_b2    = (const float*)d_in[22];
    float* out = (float*)d_out;

    k_pre<<<160, 256>>>(g0_We, g0_ae, g1_We, g1_ae,
                        g0_W, g0_asrc, g0_adst, g1_W, g1_asrc, g1_adst);
    k_ln_node<<<NN / 8, 256>>>(node_x, ln_ng, ln_nb);
    k_ln_edge<<<GE / 256, 256>>>(edge_attr, ln_eg, ln_eb, edge_idx);
    k_assign<<<(NN + 255) / 256, 256>>>();
    k_scatter<<<GE / 256, 256>>>(edge_idx);

    k_proj0<<<NN / 8, 256>>>(g0_W);
    k_agg0<<<NN / 8, 256>>>(g0_b);
    k_proj1<<<NN / 8, 256>>>(g1_W);
    k_agg1<<<NN / 8, 256>>>(g1_b);

    k_pool_partial<<<64, 256>>>();
    k_D<<<BB, 128>>>(mlp_W1, mlp_b1);
    k_AB<<<1184, 256>>>(mlp_W1);
    k_final<<<1184, 256>>>(edge_idx, mlp_W1, mlp_W2, mlp_b2, out);
}

// round 5
// speedup vs baseline: 1.6760x; 1.0276x over previous
#include <cuda_runtime.h>
#include <cuda_fp16.h>
#include <math.h>

#define BB    8
#define NPG   5000
#define EPG   80000
#define NN    40000
#define GE    640000
#define HID   128
#define EMB   64

// ---------------- scratch (static device arrays) ---------------------------
__device__ float d_nx[NN * 32];
__device__ float d_nef[GE * 16];
__device__ float d_ee0[GE], d_ee1[GE];
__device__ int   d_gsrc[GE];
__device__ int   d_cnt[NN], d_beg[NN], d_cur[NN], d_csr[GE];
__device__ int   d_ctr;
__device__ __half d_h0[NN * HID];          // fp16: gathered in agg0
__device__ float d_s0s[NN], d_s0d[NN];
__device__ float d_g0[NN * HID];
__device__ __half d_h1[NN * EMB];          // fp16: gathered in agg1
__device__ float d_s1s[NN], d_s1d[NN];
__device__ float d_emb[NN * EMB];
__device__ __half d_A[NN * HID];           // fp16: gathered in final
__device__ __half d_Bm[NN * HID];          // fp16: gathered in final
__device__ float d_D[BB * HID];
__device__ float d_wae0[16], d_wae1[16];
__device__ float d_was0[32], d_wad0[32];
__device__ float d_was1[128], d_wad1[128];
__device__ float d_psum[BB * 8 * 64];
__device__ unsigned d_pmax[BB * 64];

__device__ __forceinline__ unsigned encf(float f) {
    unsigned u = __float_as_uint(f);
    return (u & 0x80000000u) ? ~u : (u | 0x80000000u);
}
__device__ __forceinline__ float decf(unsigned e) {
    return (e & 0x80000000u) ? __uint_as_float(e ^ 0x80000000u) : __uint_as_float(~e);
}

// ------------- k_pre: zero counters + precompute folded weight vectors ------
__global__ void k_pre(const float* __restrict__ We0, const float* __restrict__ ae0,
                      const float* __restrict__ We1, const float* __restrict__ ae1,
                      const float* __restrict__ W0,  const float* __restrict__ as0,
                      const float* __restrict__ ad0, const float* __restrict__ W1g,
                      const float* __restrict__ as1, const float* __restrict__ ad1)
{
    int t = blockIdx.x * blockDim.x + threadIdx.x;
    int stride = gridDim.x * blockDim.x;
    for (int i = t; i < NN; i += stride) d_cnt[i] = 0;
    for (int i = t; i < BB * 64; i += stride) d_pmax[i] = encf(-1e30f);
    if (t == 0) d_ctr = 0;
    if (blockIdx.x == 0) {
        int tt = threadIdx.x;
        if (tt < 16) {
            float s = 0.f;
            for (int c = 0; c < 128; c++) s += We0[tt * 128 + c] * ae0[c];
            d_wae0[tt] = s;
        } else if (tt < 32) {
            int k = tt - 16;
            float s = 0.f;
            for (int c = 0; c < 64; c++) s += We1[k * 64 + c] * ae1[c];
            d_wae1[k] = s;
        } else if (tt < 64) {
            int k = tt - 32;
            float s0 = 0.f, s1 = 0.f;
            for (int c = 0; c < 128; c++) {
                float w = W0[k * 128 + c];
                s0 += w * as0[c]; s1 += w * ad0[c];
            }
            d_was0[k] = s0; d_wad0[k] = s1;
        }
    } else if (blockIdx.x == 1) {
        int tt = threadIdx.x;
        if (tt < 128) {
            float s0 = 0.f, s1 = 0.f;
            for (int c = 0; c < 64; c++) {
                float w = W1g[tt * 64 + c];
                s0 += w * as1[c]; s1 += w * ad1[c];
            }
            d_was1[tt] = s0; d_wad1[tt] = s1;
        }
    }
}

// ------------- node layernorm + folded s0s/s0d: warp per node ---------------
__global__ void k_ln_node(const float* __restrict__ x, const float* __restrict__ g,
                          const float* __restrict__ b)
{
    int warp = threadIdx.x >> 5, lane = threadIdx.x & 31;
    int n = blockIdx.x * 8 + warp;
    if (n >= NN) return;
    float v = x[n * 32 + lane];
    float mu = v;
    #pragma unroll
    for (int o = 16; o; o >>= 1) mu += __shfl_xor_sync(~0u, mu, o);
    mu *= (1.f / 32.f);
    float d = v - mu;
    float var = d * d;
    #pragma unroll
    for (int o = 16; o; o >>= 1) var += __shfl_xor_sync(~0u, var, o);
    var *= (1.f / 32.f);
    float y = d * rsqrtf(var + 1e-5f) * g[lane] + b[lane];
    d_nx[n * 32 + lane] = y;
    float ps = y * d_was0[lane], pd = y * d_wad0[lane];
    #pragma unroll
    for (int o = 16; o; o >>= 1) {
        ps += __shfl_xor_sync(~0u, ps, o);
        pd += __shfl_xor_sync(~0u, pd, o);
    }
    if (lane == 0) { d_s0s[n] = ps; d_s0d[n] = pd; }
}

// ------- edge layernorm (float4) + logit terms + gsrc + degree count --------
__global__ void k_ln_edge(const float* __restrict__ ea, const float* __restrict__ g,
                          const float* __restrict__ b, const int* __restrict__ ei)
{
    __shared__ float sg[16], sb[16], sw0[16], sw1[16];
    if (threadIdx.x < 16) {
        sg[threadIdx.x] = g[threadIdx.x];
        sb[threadIdx.x] = b[threadIdx.x];
        sw0[threadIdx.x] = d_wae0[threadIdx.x];
        sw1[threadIdx.x] = d_wae1[threadIdx.x];
    }
    __syncthreads();
    int ge = blockIdx.x * 256 + threadIdx.x;
    if (ge >= GE) return;
    int bb = ge / EPG;
    int e  = ge - bb * EPG;
    int src = ei[e] + bb * NPG;
    int dst = ei[EPG + e] + bb * NPG;
    d_gsrc[ge] = src;
    atomicAdd(&d_cnt[dst], 1);

    const float4* rp = (const float4*)(ea + (size_t)ge * 16);
    float4 q[4];
    q[0] = rp[0]; q[1] = rp[1]; q[2] = rp[2]; q[3] = rp[3];
    float* v = (float*)q;
    float mu = 0.f;
    #pragma unroll
    for (int k = 0; k < 16; k++) mu += v[k];
    mu *= (1.f / 16.f);
    float var = 0.f;
    #pragma unroll
    for (int k = 0; k < 16; k++) { float d = v[k] - mu; var += d * d; }
    var *= (1.f / 16.f);
    float r = rsqrtf(var + 1e-5f);
    float e0 = 0.f, e1 = 0.f;
    #pragma unroll
    for (int k = 0; k < 16; k++) {
        float y = (v[k] - mu) * r * sg[k] + sb[k];
        v[k] = y;
        e0 += y * sw0[k];
        e1 += y * sw1[k];
    }
    float4* wp = (float4*)(d_nef + (size_t)ge * 16);
    wp[0] = q[0]; wp[1] = q[1]; wp[2] = q[2]; wp[3] = q[3];
    d_ee0[ge] = e0;
    d_ee1[ge] = e1;
}

// -------- segment assignment (order-free) + scatter --------------------------
__global__ void k_assign()
{
    int n = blockIdx.x * 256 + threadIdx.x;
    if (n >= NN) return;
    int deg = d_cnt[n];
    int beg = atomicAdd(&d_ctr, deg);
    d_beg[n] = beg;
    d_cur[n] = beg;
}

__global__ void k_scatter(const int* __restrict__ ei)
{
    int ge = blockIdx.x * 256 + threadIdx.x;
    if (ge >= GE) return;
    int bb = ge / EPG;
    int e  = ge - bb * EPG;
    int dst = ei[EPG + e] + bb * NPG;
    int pos = atomicAdd(&d_cur[dst], 1);
    d_csr[pos] = ge;
}

// -------- proj0: GEMM 40000x32 -> 128 (fp16 out), 8 nodes/block --------------
__global__ void k_proj0(const float* __restrict__ W)
{
    __shared__ float sin_[8 * 32];
    int t = threadIdx.x;
    int n0 = blockIdx.x * 8;
    sin_[t] = d_nx[n0 * 32 + t];
    __syncthreads();
    int c = t & 127, gidx = t >> 7;
    float a0 = 0.f, a1 = 0.f, a2 = 0.f, a3 = 0.f;
    #pragma unroll
    for (int k = 0; k < 32; k++) {
        float w = W[k * 128 + c];
        a0 += sin_[(gidx * 4 + 0) * 32 + k] * w;
        a1 += sin_[(gidx * 4 + 1) * 32 + k] * w;
        a2 += sin_[(gidx * 4 + 2) * 32 + k] * w;
        a3 += sin_[(gidx * 4 + 3) * 32 + k] * w;
    }
    int nb = n0 + gidx * 4;
    d_h0[(size_t)(nb + 0) * 128 + c] = __float2half_rn(a0);
    d_h0[(size_t)(nb + 1) * 128 + c] = __float2half_rn(a1);
    d_h0[(size_t)(nb + 2) * 128 + c] = __float2half_rn(a2);
    d_h0[(size_t)(nb + 3) * 128 + c] = __float2half_rn(a3);
}

// -------- proj1: GEMM 40000x128 -> 64 (fp16 out), 8 nodes/block --------------
__global__ void k_proj1(const float* __restrict__ W)
{
    __shared__ float sin_[8 * 128];
    int t = threadIdx.x;
    int n0 = blockIdx.x * 8;
    #pragma unroll
    for (int i = t; i < 8 * 128; i += 256) sin_[i] = d_g0[(size_t)n0 * 128 + i];
    __syncthreads();
    int c = t & 63, gidx = t >> 6;
    float a0 = 0.f, a1 = 0.f;
    #pragma unroll 8
    for (int k = 0; k < 128; k++) {
        float w = W[k * 64 + c];
        a0 += sin_[(gidx * 2 + 0) * 128 + k] * w;
        a1 += sin_[(gidx * 2 + 1) * 128 + k] * w;
    }
    int nb = n0 + gidx * 2;
    d_h1[(size_t)(nb + 0) * 64 + c] = __float2half_rn(a0);
    d_h1[(size_t)(nb + 1) * 64 + c] = __float2half_rn(a1);
}

// -------- fp16 gather helpers ------------------------------------------------
template<int K>
__device__ __forceinline__ void gatherH(float* acc, const __half* __restrict__ h,
                                        int S, float A, int lane)
{
    if constexpr (K == 4) {
        uint2 u = *(const uint2*)(h + (size_t)S * 128 + lane * 4);
        float2 f01 = __half22float2(*(__half2*)&u.x);
        float2 f23 = __half22float2(*(__half2*)&u.y);
        acc[0] += A * f01.x; acc[1] += A * f01.y;
        acc[2] += A * f23.x; acc[3] += A * f23.y;
    } else {
        __half2 hv = *(const __half2*)(h + (size_t)S * 64 + lane * 2);
        float2 f = __half22float2(hv);
        acc[0] += A * f.x; acc[1] += A * f.y;
    }
}

// -------- GAT aggregation: warp per dst node ---------------------------------
template<int OUT, bool DOELU, bool DOS1, bool H16OUT>
__device__ __forceinline__ void agg_body(const __half* __restrict__ h,
                                         const float* __restrict__ ss,
                                         const float* __restrict__ sd,
                                         const float* __restrict__ ee,
                                         const float* __restrict__ bias,
                                         float* __restrict__ outf)
{
    int warp = threadIdx.x >> 5, lane = threadIdx.x & 31;
    int n = blockIdx.x * 8 + warp;
    if (n >= NN) return;
    int beg = d_beg[n], deg = d_cnt[n];
    constexpr int K = OUT / 32;
    float acc[K];
    #pragma unroll
    for (int u = 0; u < K; u++) acc[u] = 0.f;

    if (deg > 0) {
        float sdv = sd[n];
        if (deg <= 32) {
            int src = 0;
            float lg = -1e30f;
            if (lane < deg) {
                int ge = d_csr[beg + lane];
                src = d_gsrc[ge];
                lg = ss[src] + sdv + ee[ge];
                lg = lg > 0.f ? lg : 0.2f * lg;
            }
            float M = lg;
            #pragma unroll
            for (int o = 16; o; o >>= 1) M = fmaxf(M, __shfl_xor_sync(~0u, M, o));
            float ex = (lane < deg) ? __expf(lg - M) : 0.f;
            float sm = ex;
            #pragma unroll
            for (int o = 16; o; o >>= 1) sm += __shfl_xor_sync(~0u, sm, o);
            float alpha = ex / (sm + 1e-16f);
            for (int j = 0; j < deg; j += 8) {
                #pragma unroll
                for (int q = 0; q < 8; q++) {
                    float A = __shfl_sync(~0u, alpha, j + q);
                    int S   = __shfl_sync(~0u, src, j + q);
                    gatherH<K>(acc, h, S, A, lane);   // alpha=0 for j+q>=deg
                }
            }
        } else {
            float m = -1e30f, sm = 0.f;
            for (int i = lane; i < deg; i += 32) {
                int ge = d_csr[beg + i];
                float lg = ss[d_gsrc[ge]] + sdv + ee[ge];
                lg = lg > 0.f ? lg : 0.2f * lg;
                float nm = fmaxf(m, lg);
                sm = sm * __expf(m - nm) + __expf(lg - nm);
                m = nm;
            }
            float M = m;
            #pragma unroll
            for (int o = 16; o; o >>= 1) M = fmaxf(M, __shfl_xor_sync(~0u, M, o));
            sm *= __expf(m - M);
            #pragma unroll
            for (int o = 16; o; o >>= 1) sm += __shfl_xor_sync(~0u, sm, o);
            float inv = 1.f / (sm + 1e-16f);
            for (int base = 0; base < deg; base += 32) {
                int i = base + lane;
                float alpha = 0.f;
                int src = 0;
                if (i < deg) {
                    int ge = d_csr[beg + i];
                    src = d_gsrc[ge];
                    float lg = ss[src] + sdv + ee[ge];
                    lg = lg > 0.f ? lg : 0.2f * lg;
                    alpha = __expf(lg - M) * inv;
                }
                int cnt = min(32, deg - base);
                for (int j = 0; j < cnt; j += 8) {
                    #pragma unroll
                    for (int q = 0; q < 8; q++) {
                        float A = __shfl_sync(~0u, alpha, j + q);
                        int S   = __shfl_sync(~0u, src, j + q);
                        gatherH<K>(acc, h, S, A, lane);
                    }
                }
            }
        }
    }
    float v[K];
    #pragma unroll
    for (int u = 0; u < K; u++) {
        v[u] = acc[u] + bias[lane * K + u];
        if (DOELU) v[u] = v[u] > 0.f ? v[u] : expm1f(v[u]);
        outf[(size_t)n * OUT + lane * K + u] = v[u];
    }
    if (DOS1) {
        float ps = 0.f, pd = 0.f;
        #pragma unroll
        for (int u = 0; u < K; u++) {
            ps += v[u] * d_was1[lane * K + u];
            pd += v[u] * d_wad1[lane * K + u];
        }
        #pragma unroll
        for (int o = 16; o; o >>= 1) {
            ps += __shfl_xor_sync(~0u, ps, o);
            pd += __shfl_xor_sync(~0u, pd, o);
        }
        if (lane == 0) { d_s1s[n] = ps; d_s1d[n] = pd; }
    }
}

__global__ void k_agg0(const float* __restrict__ bias)
{
    agg_body<HID, true, true, false>(d_h0, d_s0s, d_s0d, d_ee0, bias, d_g0);
}
__global__ void k_agg1(const float* __restrict__ bias)
{
    agg_body<EMB, false, false, false>(d_h1, d_s1s, d_s1d, d_ee1, bias, d_emb);
}

// ------ pooling partials: 8 slabs per graph ---------------------------------
__global__ void k_pool_partial()
{
    int b = blockIdx.x >> 3, slab = blockIdx.x & 7;
    int t = threadIdx.x;
    int c = t & 63, r = t >> 6;
    float sm = 0.f, mx = -1e30f;
    int nb = b * NPG + slab * 625;
    for (int i = r; i < 625; i += 4) {
        float v = d_emb[(size_t)(nb + i) * 64 + c];
        sm += v;
        mx = fmaxf(mx, v);
    }
    __shared__ float sS[4][64], sM[4][64];
    sS[r][c] = sm; sM[r][c] = mx;
    __syncthreads();
    if (r == 0) {
        float s = sS[0][c] + sS[1][c] + sS[2][c] + sS[3][c];
        float m = fmaxf(fmaxf(sM[0][c], sM[1][c]), fmaxf(sM[2][c], sM[3][c]));
        d_psum[((size_t)b * 8 + slab) * 64 + c] = s;
        atomicMax(&d_pmax[b * 64 + c], encf(m));
    }
}

// ------ D = ctx @ W1[144:272] + b1 ------------------------------------------
__global__ void k_D(const float* __restrict__ W1, const float* __restrict__ b1)
{
    int b = blockIdx.x;
    int t = threadIdx.x;
    __shared__ float ctx[128];
    if (t < 64) {
        float s = 0.f;
        #pragma unroll
        for (int slab = 0; slab < 8; slab++) s += d_psum[((size_t)b * 8 + slab) * 64 + t];
        ctx[t] = s * (1.f / NPG);
        ctx[64 + t] = decf(d_pmax[b * 64 + t]);
    }
    __syncthreads();
    float acc = b1[t];
    for (int k = 0; k < 128; k++) acc += ctx[k] * W1[(144 + k) * 128 + t];
    d_D[b * 128 + t] = acc;
}

// ------ per-node A/B (fp16 out): warp per node -------------------------------
__global__ void k_AB(const float* __restrict__ W1)
{
    int warp = (blockIdx.x * blockDim.x + threadIdx.x) >> 5;
    int lane = threadIdx.x & 31;
    int nwarps = (gridDim.x * blockDim.x) >> 5;
    for (int n = warp; n < NN; n += nwarps) {
        float e0 = d_emb[(size_t)n * EMB + lane];
        float e1 = d_emb[(size_t)n * EMB + 32 + lane];
        float a0 = 0.f, a1 = 0.f, a2 = 0.f, a3 = 0.f;
        float b0 = 0.f, b1 = 0.f, b2 = 0.f, b3 = 0.f;
        #pragma unroll 4
        for (int k = 0; k < 64; k++) {
            float ev = __shfl_sync(~0u, (k < 32) ? e0 : e1, k & 31);
            const float* wa = W1 + k * 128;
            const float* wb = W1 + (64 + k) * 128;
            a0 += ev * wa[lane];       a1 += ev * wa[lane + 32];
            a2 += ev * wa[lane + 64];  a3 += ev * wa[lane + 96];
            b0 += ev * wb[lane];       b1 += ev * wb[lane + 32];
            b2 += ev * wb[lane + 64];  b3 += ev * wb[lane + 96];
        }
        __half* pa = d_A + (size_t)n * 128;
        __half* pb = d_Bm + (size_t)n * 128;
        pa[lane]      = __float2half_rn(a0);
        pa[lane + 32] = __float2half_rn(a1);
        pa[lane + 64] = __float2half_rn(a2);
        pa[lane + 96] = __float2half_rn(a3);
        pb[lane]      = __float2half_rn(b0);
        pb[lane + 32] = __float2half_rn(b1);
        pb[lane + 64] = __float2half_rn(b2);
        pb[lane + 96] = __float2half_rn(b3);
    }
}

// ------ final fused edge MLP: persistent, 2 edges per warp iteration ---------
__global__ void k_final(const int* __restrict__ ei, const float* __restrict__ W1,
                        const float* __restrict__ W2, const float* __restrict__ b2,
                        float* __restrict__ out)
{
    __shared__ __align__(16) float sW[16 * 128];
    __shared__ float sV[128];
    int t = threadIdx.x;
    for (int i = t; i < 16 * 128; i += 256)
        sW[i] = W1[(128 + (i >> 7)) * 128 + (i & 127)];
    if (t < 128) sV[t] = W2[t];
    __syncthreads();

    int warp = t >> 5, lane = t & 31;
    int j0 = lane * 4;
    float w2x = sV[j0], w2y = sV[j0 + 1], w2z = sV[j0 + 2], w2w = sV[j0 + 3];
    float bias2 = b2[0];
    int stride = gridDim.x * 16;

    for (int g0 = blockIdx.x * 16 + warp * 2; g0 < GE; g0 += stride) {
        int g1 = g0 + 1;
        int bb0 = g0 / EPG, e0 = g0 - bb0 * EPG;
        int bb1 = g1 / EPG, e1 = g1 - bb1 * EPG;
        int src0 = d_gsrc[g0], src1 = d_gsrc[g1];
        int dst0 = ei[EPG + e0] + bb0 * NPG;
        int dst1 = ei[EPG + e1] + bb1 * NPG;

        float ef2 = d_nef[(size_t)g0 * 16 + lane];

        uint2 ua0 = *(const uint2*)(d_A  + (size_t)src0 * 128 + j0);
        uint2 ua1 = *(const uint2*)(d_A  + (size_t)src1 * 128 + j0);
        uint2 ub0 = *(const uint2*)(d_Bm + (size_t)dst0 * 128 + j0);
        uint2 ub1 = *(const uint2*)(d_Bm + (size_t)dst1 * 128 + j0);
        float4 vd0 = *(const float4*)(d_D + bb0 * 128 + j0);
        float4 vd1 = *(const float4*)(d_D + bb1 * 128 + j0);

        float2 a0lo = __half22float2(*(__half2*)&ua0.x), a0hi = __half22float2(*(__half2*)&ua0.y);
        float2 a1lo = __half22float2(*(__half2*)&ua1.x), a1hi = __half22float2(*(__half2*)&ua1.y);
        float2 b0lo = __half22float2(*(__half2*)&ub0.x), b0hi = __half22float2(*(__half2*)&ub0.y);
        float2 b1lo = __half22float2(*(__half2*)&ub1.x), b1hi = __half22float2(*(__half2*)&ub1.y);

        float4 v0, v1;
        v0.x = a0lo.x + b0lo.x + vd0.x; v0.y = a0lo.y + b0lo.y + vd0.y;
        v0.z = a0hi.x + b0hi.x + vd0.z; v0.w = a0hi.y + b0hi.y + vd0.w;
        v1.x = a1lo.x + b1lo.x + vd1.x; v1.y = a1lo.y + b1lo.y + vd1.y;
        v1.z = a1hi.x + b1hi.x + vd1.z; v1.w = a1hi.y + b1hi.y + vd1.w;
        #pragma unroll
        for (int k = 0; k < 16; k++) {
            float ek0 = __shfl_sync(~0u, ef2, k);
            float ek1 = __shfl_sync(~0u, ef2, 16 + k);
            float4 w = *(const float4*)(sW + k * 128 + j0);
            v0.x += ek0 * w.x; v0.y += ek0 * w.y; v0.z += ek0 * w.z; v0.w += ek0 * w.w;
            v1.x += ek1 * w.x; v1.y += ek1 * w.y; v1.z += ek1 * w.z; v1.w += ek1 * w.w;
        }
        float p0 = fmaxf(v0.x, 0.f) * w2x + fmaxf(v0.y, 0.f) * w2y
                 + fmaxf(v0.z, 0.f) * w2z + fmaxf(v0.w, 0.f) * w2w;
        float p1 = fmaxf(v1.x, 0.f) * w2x + fmaxf(v1.y, 0.f) * w2y
                 + fmaxf(v1.z, 0.f) * w2z + fmaxf(v1.w, 0.f) * w2w;
        #pragma unroll
        for (int o = 16; o; o >>= 1) {
            p0 += __shfl_xor_sync(~0u, p0, o);
            p1 += __shfl_xor_sync(~0u, p1, o);
        }
        if (lane == 0) {
            float2 r; r.x = p0 + bias2; r.y = p1 + bias2;
            *(float2*)(out + g0) = r;
        }
    }
}

// ---------------------------------------------------------------------------
extern "C" void kernel_launch(void* const* d_in, const int* in_sizes, int n_in,
                              void* d_out, int out_size)
{
    const float* node_x    = (const float*)d_in[0];
    const float* edge_attr = (const float*)d_in[1];
    const int*   edge_idx  = (const int*)  d_in[2];
    const float* ln_ng     = (const float*)d_in[3];
    const float* ln_nb     = (const float*)d_in[4];
    const float* ln_eg     = (const float*)d_in[5];
    const float* ln_eb     = (const float*)d_in[6];
    const float* g0_W      = (const float*)d_in[7];
    const float* g0_We     = (const float*)d_in[8];
    const float* g0_asrc   = (const float*)d_in[9];
    const float* g0_adst   = (const float*)d_in[10];
    const float* g0_ae     = (const float*)d_in[11];
    const float* g0_b      = (const float*)d_in[12];
    const float* g1_W      = (const float*)d_in[13];
    const float* g1_We     = (const float*)d_in[14];
    const float* g1_asrc   = (const float*)d_in[15];
    const float* g1_adst   = (const float*)d_in[16];
    const float* g1_ae     = (const float*)d_in[17];
    const float* g1_b      = (const float*)d_in[18];
    const float* mlp_W1    = (const float*)d_in[19];
    const float* mlp_b1    = (const float*)d_in[20];
    const float* mlp_W2    = (const float*)d_in[21];
    const float* mlp_b2    = (const float*)d_in[22];
    float* out = (float*)d_out;

    k_pre<<<160, 256>>>(g0_We, g0_ae, g1_We, g1_ae,
                        g0_W, g0_asrc, g0_adst, g1_W, g1_asrc, g1_adst);
    k_ln_node<<<NN / 8, 256>>>(node_x, ln_ng, ln_nb);
    k_ln_edge<<<GE / 256, 256>>>(edge_attr, ln_eg, ln_eb, edge_idx);
    k_assign<<<(NN + 255) / 256, 256>>>();
    k_scatter<<<GE / 256, 256>>>(edge_idx);

    k_proj0<<<NN / 8, 256>>>(g0_W);
    k_agg0<<<NN / 8, 256>>>(g0_b);
    k_proj1<<<NN / 8, 256>>>(g1_W);
    k_agg1<<<NN / 8, 256>>>(g1_b);

    k_pool_partial<<<64, 256>>>();
    k_D<<<BB, 128>>>(mlp_W1, mlp_b1);
    k_AB<<<1184, 256>>>(mlp_W1);
    k_final<<<1184, 256>>>(edge_idx, mlp_W1, mlp_W2, mlp_b2, out);
}

// round 6
// speedup vs baseline: 1.8239x; 1.0883x over previous
#include <cuda_runtime.h>
#include <cuda_fp16.h>
#include <math.h>

#define BB    8
#define NPG   5000
#define EPG   80000
#define NN    40000
#define GE    640000
#define HID   128
#define EMB   64

// ---------------- scratch (static device arrays) ---------------------------
__device__ int   d_cnt[NPG], d_beg[NPG], d_cur[NPG];
__device__ int   d_csr[EPG];        // pos -> local edge id
__device__ int   d_slot[EPG];       // local edge id -> pos
__device__ int   d_srcp[EPG];       // pos -> local src node
__device__ int   d_ctr;
__device__ float d_ee0p[GE], d_ee1p[GE];      // permuted per-edge logit terms
__device__ __half d_nefp[GE * 16];            // permuted fp16 edge features
__device__ __half d_h0[NN * HID];
__device__ float d_s0s[NN], d_s0d[NN];
__device__ __half d_h1[NN * EMB];
__device__ float d_s1s[NN], d_s1d[NN];
__device__ float d_emb[NN * EMB];
__device__ __half d_A[NN * HID], d_Bm[NN * HID];
__device__ float d_D[BB * HID];
__device__ float d_wae0[16], d_wae1[16];
__device__ float d_was0[32], d_wad0[32];
__device__ float d_was1[128], d_wad1[128];
__device__ float d_psum[5000 * 64];           // per-block pooling partials
__device__ float d_pmaxf[5000 * 64];

// ------------- k_pre: zero counters + precompute folded weight vectors ------
__global__ void k_pre(const float* __restrict__ We0, const float* __restrict__ ae0,
                      const float* __restrict__ We1, const float* __restrict__ ae1,
                      const float* __restrict__ W0,  const float* __restrict__ as0,
                      const float* __restrict__ ad0, const float* __restrict__ W1g,
                      const float* __restrict__ as1, const float* __restrict__ ad1)
{
    int t = blockIdx.x * blockDim.x + threadIdx.x;
    int stride = gridDim.x * blockDim.x;
    for (int i = t; i < NPG; i += stride) d_cnt[i] = 0;
    if (t == 0) d_ctr = 0;
    if (blockIdx.x == 0) {
        int tt = threadIdx.x;
        if (tt < 16) {
            float s = 0.f;
            for (int c = 0; c < 128; c++) s += We0[tt * 128 + c] * ae0[c];
            d_wae0[tt] = s;
        } else if (tt < 32) {
            int k = tt - 16;
            float s = 0.f;
            for (int c = 0; c < 64; c++) s += We1[k * 64 + c] * ae1[c];
            d_wae1[k] = s;
        } else if (tt < 64) {
            int k = tt - 32;
            float s0 = 0.f, s1 = 0.f;
            for (int c = 0; c < 128; c++) {
                float w = W0[k * 128 + c];
                s0 += w * as0[c]; s1 += w * ad0[c];
            }
            d_was0[k] = s0; d_wad0[k] = s1;
        }
    } else if (blockIdx.x == 1) {
        int tt = threadIdx.x;
        if (tt < 128) {
            float s0 = 0.f, s1 = 0.f;
            for (int c = 0; c < 64; c++) {
                float w = W1g[tt * 64 + c];
                s0 += w * as1[c]; s1 += w * ad1[c];
            }
            d_was1[tt] = s0; d_wad1[tt] = s1;
        }
    }
}

// ---- CSR build on ONE graph (shared across batch) --------------------------
__global__ void k_count(const int* __restrict__ ei)
{
    int el = blockIdx.x * 256 + threadIdx.x;
    if (el < EPG) atomicAdd(&d_cnt[ei[EPG + el]], 1);
}

__global__ void k_assign()
{
    int n = blockIdx.x * 256 + threadIdx.x;
    if (n >= NPG) return;
    int deg = d_cnt[n];
    int beg = atomicAdd(&d_ctr, deg);
    d_beg[n] = beg;
    d_cur[n] = beg;
}

__global__ void k_scatter(const int* __restrict__ ei)
{
    int el = blockIdx.x * 256 + threadIdx.x;
    if (el >= EPG) return;
    int dst = ei[EPG + el];
    int pos = atomicAdd(&d_cur[dst], 1);
    d_csr[pos] = el;
    d_slot[el] = pos;
    d_srcp[pos] = ei[el];
}

// ------- edge layernorm -> permuted fp16 ef + logit terms -------------------
__global__ void k_ln_edge(const float* __restrict__ ea, const float* __restrict__ g,
                          const float* __restrict__ b)
{
    __shared__ float sg[16], sb[16], sw0[16], sw1[16];
    if (threadIdx.x < 16) {
        sg[threadIdx.x] = g[threadIdx.x];
        sb[threadIdx.x] = b[threadIdx.x];
        sw0[threadIdx.x] = d_wae0[threadIdx.x];
        sw1[threadIdx.x] = d_wae1[threadIdx.x];
    }
    __syncthreads();
    int ge = blockIdx.x * 256 + threadIdx.x;
    if (ge >= GE) return;
    int bb = ge / EPG;
    int el = ge - bb * EPG;
    int pos = d_slot[el];
    size_t base = (size_t)bb * EPG + pos;

    const float4* rp = (const float4*)(ea + (size_t)ge * 16);
    float4 q[4];
    q[0] = rp[0]; q[1] = rp[1]; q[2] = rp[2]; q[3] = rp[3];
    float* v = (float*)q;
    float mu = 0.f;
    #pragma unroll
    for (int k = 0; k < 16; k++) mu += v[k];
    mu *= (1.f / 16.f);
    float var = 0.f;
    #pragma unroll
    for (int k = 0; k < 16; k++) { float d = v[k] - mu; var += d * d; }
    var *= (1.f / 16.f);
    float r = rsqrtf(var + 1e-5f);
    float e0 = 0.f, e1 = 0.f;
    __half2 hh[8];
    #pragma unroll
    for (int k = 0; k < 16; k += 2) {
        float y0 = (v[k] - mu) * r * sg[k] + sb[k];
        float y1 = (v[k + 1] - mu) * r * sg[k + 1] + sb[k + 1];
        e0 += y0 * sw0[k] + y1 * sw0[k + 1];
        e1 += y0 * sw1[k] + y1 * sw1[k + 1];
        hh[k >> 1] = __floats2half2_rn(y0, y1);
    }
    uint4* wp = (uint4*)(d_nefp + base * 16);
    wp[0] = *(uint4*)&hh[0];
    wp[1] = *(uint4*)&hh[4];
    d_ee0p[base] = e0;
    d_ee1p[base] = e1;
}

// ------ fused node layernorm + proj0 + folded s0s/s0d: warp per node --------
__global__ void k_lnproj0(const float* __restrict__ x, const float* __restrict__ g,
                          const float* __restrict__ b, const float* __restrict__ W)
{
    int warp = threadIdx.x >> 5, lane = threadIdx.x & 31;
    int n = blockIdx.x * 8 + warp;
    float v = x[n * 32 + lane];
    float mu = v;
    #pragma unroll
    for (int o = 16; o; o >>= 1) mu += __shfl_xor_sync(~0u, mu, o);
    mu *= (1.f / 32.f);
    float d = v - mu;
    float var = d * d;
    #pragma unroll
    for (int o = 16; o; o >>= 1) var += __shfl_xor_sync(~0u, var, o);
    var *= (1.f / 32.f);
    float y = d * rsqrtf(var + 1e-5f) * g[lane] + b[lane];

    float ps = y * d_was0[lane], pd = y * d_wad0[lane];
    #pragma unroll
    for (int o = 16; o; o >>= 1) {
        ps += __shfl_xor_sync(~0u, ps, o);
        pd += __shfl_xor_sync(~0u, pd, o);
    }
    if (lane == 0) { d_s0s[n] = ps; d_s0d[n] = pd; }

    float a0 = 0.f, a1 = 0.f, a2 = 0.f, a3 = 0.f;
    #pragma unroll 8
    for (int k = 0; k < 32; k++) {
        float yk = __shfl_sync(~0u, y, k);
        float4 w = *(const float4*)(W + k * 128 + lane * 4);
        a0 += yk * w.x; a1 += yk * w.y; a2 += yk * w.z; a3 += yk * w.w;
    }
    __half2 h01 = __floats2half2_rn(a0, a1);
    __half2 h23 = __floats2half2_rn(a2, a3);
    uint2 u; u.x = *(unsigned*)&h01; u.y = *(unsigned*)&h23;
    *(uint2*)(d_h0 + (size_t)n * 128 + lane * 4) = u;
}

// -------- fp16 gather helper -------------------------------------------------
template<int K>
__device__ __forceinline__ void gatherH(float* acc, const __half* __restrict__ h,
                                        int S, float A, int lane)
{
    if constexpr (K == 4) {
        uint2 u = *(const uint2*)(h + (size_t)S * 128 + lane * 4);
        float2 f01 = __half22float2(*(__half2*)&u.x);
        float2 f23 = __half22float2(*(__half2*)&u.y);
        acc[0] += A * f01.x; acc[1] += A * f01.y;
        acc[2] += A * f23.x; acc[3] += A * f23.y;
    } else {
        __half2 hv = *(const __half2*)(h + (size_t)S * 64 + lane * 2);
        float2 f = __half22float2(hv);
        acc[0] += A * f.x; acc[1] += A * f.y;
    }
}

// -------- shared softmax+gather core ------------------------------------------
template<int K>
__device__ __forceinline__ void agg_core(float* acc, const __half* __restrict__ h,
                                         const float* __restrict__ ss,
                                         const float* __restrict__ eep,
                                         float sdv, int b, int beg, int deg,
                                         size_t ebase, int lane)
{
    if (deg <= 32) {
        int src = 0;
        float lg = -1e30f;
        if (lane < deg) {
            int sl = d_srcp[beg + lane];
            src = b * NPG + sl;
            lg = ss[src] + sdv + eep[ebase + lane];
            lg = lg > 0.f ? lg : 0.2f * lg;
        }
        float M = lg;
        #pragma unroll
        for (int o = 16; o; o >>= 1) M = fmaxf(M, __shfl_xor_sync(~0u, M, o));
        float ex = (lane < deg) ? __expf(lg - M) : 0.f;
        float sm = ex;
        #pragma unroll
        for (int o = 16; o; o >>= 1) sm += __shfl_xor_sync(~0u, sm, o);
        float alpha = ex / (sm + 1e-16f);
        for (int j = 0; j < deg; j += 8) {
            #pragma unroll
            for (int q = 0; q < 8; q++) {
                float A = __shfl_sync(~0u, alpha, j + q);
                int S   = __shfl_sync(~0u, src, j + q);
                gatherH<K>(acc, h, S, A, lane);
            }
        }
    } else {
        float m = -1e30f, sm = 0.f;
        for (int i = lane; i < deg; i += 32) {
            int sl = d_srcp[beg + i];
            float lg = ss[b * NPG + sl] + sdv + eep[ebase + i];
            lg = lg > 0.f ? lg : 0.2f * lg;
            float nm = fmaxf(m, lg);
            sm = sm * __expf(m - nm) + __expf(lg - nm);
            m = nm;
        }
        float M = m;
        #pragma unroll
        for (int o = 16; o; o >>= 1) M = fmaxf(M, __shfl_xor_sync(~0u, M, o));
        sm *= __expf(m - M);
        #pragma unroll
        for (int o = 16; o; o >>= 1) sm += __shfl_xor_sync(~0u, sm, o);
        float inv = 1.f / (sm + 1e-16f);
        for (int basei = 0; basei < deg; basei += 32) {
            int i = basei + lane;
            float alpha = 0.f;
            int src = 0;
            if (i < deg) {
                int sl = d_srcp[beg + i];
                src = b * NPG + sl;
                float lg = ss[src] + sdv + eep[ebase + i];
                lg = lg > 0.f ? lg : 0.2f * lg;
                alpha = __expf(lg - M) * inv;
            }
            int cnt = min(32, deg - basei);
            for (int j = 0; j < cnt; j += 8) {
                #pragma unroll
                for (int q = 0; q < 8; q++) {
                    float A = __shfl_sync(~0u, alpha, j + q);
                    int S   = __shfl_sync(~0u, src, j + q);
                    gatherH<K>(acc, h, S, A, lane);
                }
            }
        }
    }
}

// -------- agg0 fused with proj1 ------------------------------------------------
__global__ void k_agg0(const float* __restrict__ bias, const float* __restrict__ W1g)
{
    __shared__ float sg0[8][128];
    int warp = threadIdx.x >> 5, lane = threadIdx.x & 31;
    int n = blockIdx.x * 8 + warp;
    int b = n / NPG, ln = n - b * NPG;
    int beg = d_beg[ln], deg = d_cnt[ln];
    size_t ebase = (size_t)b * EPG + beg;
    float acc[4] = {0.f, 0.f, 0.f, 0.f};
    if (deg > 0)
        agg_core<4>(acc, d_h0, d_s0s, d_ee0p, d_s0d[n], b, beg, deg, ebase, lane);

    float v[4];
    float ps = 0.f, pd = 0.f;
    #pragma unroll
    for (int u = 0; u < 4; u++) {
        float t = acc[u] + bias[lane * 4 + u];
        t = t > 0.f ? t : expm1f(t);
        v[u] = t;
        sg0[warp][lane * 4 + u] = t;
        ps += t * d_was1[lane * 4 + u];
        pd += t * d_wad1[lane * 4 + u];
    }
    #pragma unroll
    for (int o = 16; o; o >>= 1) {
        ps += __shfl_xor_sync(~0u, ps, o);
        pd += __shfl_xor_sync(~0u, pd, o);
    }
    if (lane == 0) { d_s1s[n] = ps; d_s1d[n] = pd; }
    __syncwarp();

    // proj1: h1[c2] for c2 = lane*2, lane*2+1
    float a0 = 0.f, a1 = 0.f;
    const float* row = sg0[warp];
    #pragma unroll 4
    for (int k = 0; k < 128; k++) {
        float gv = row[k];
        float2 w = *(const float2*)(W1g + k * 64 + lane * 2);
        a0 += gv * w.x; a1 += gv * w.y;
    }
    __half2 hh = __floats2half2_rn(a0, a1);
    *(__half2*)(d_h1 + (size_t)n * 64 + lane * 2) = hh;
}

// -------- agg1 fused with pooling partials --------------------------------------
__global__ void k_agg1(const float* __restrict__ bias)
{
    __shared__ float semb[8][64];
    int warp = threadIdx.x >> 5, lane = threadIdx.x & 31;
    int n = blockIdx.x * 8 + warp;
    int b = n / NPG, ln = n - b * NPG;
    int beg = d_beg[ln], deg = d_cnt[ln];
    size_t ebase = (size_t)b * EPG + beg;
    float acc[2] = {0.f, 0.f};
    if (deg > 0)
        agg_core<2>(acc, d_h1, d_s1s, d_ee1p, d_s1d[n], b, beg, deg, ebase, lane);

    float v0 = acc[0] + bias[lane * 2];
    float v1 = acc[1] + bias[lane * 2 + 1];
    float2 f2; f2.x = v0; f2.y = v1;
    *(float2*)(d_emb + (size_t)n * 64 + lane * 2) = f2;
    semb[warp][lane * 2] = v0;
    semb[warp][lane * 2 + 1] = v1;
    __syncthreads();
    int t = threadIdx.x;
    if (t < 64) {
        float s = 0.f, m = -1e30f;
        #pragma unroll
        for (int r = 0; r < 8; r++) {
            float x = semb[r][t];
            s += x; m = fmaxf(m, x);
        }
        d_psum[blockIdx.x * 64 + t] = s;
        d_pmaxf[blockIdx.x * 64 + t] = m;
    }
}

// ------ D = ctx @ W1[144:272] + b1 ------------------------------------------
__global__ void k_D(const float* __restrict__ W1, const float* __restrict__ b1)
{
    int g = blockIdx.x;
    int t = threadIdx.x;                 // 128
    __shared__ float ctx[128];
    if (t < 64) {
        float s = 0.f, m = -1e30f;
        for (int i = 0; i < 625; i++) {
            int idx = (g * 625 + i) * 64 + t;
            s += d_psum[idx];
            m = fmaxf(m, d_pmaxf[idx]);
        }
        ctx[t] = s * (1.f / NPG);
        ctx[64 + t] = m;
    }
    __syncthreads();
    float acc = b1[t];
    for (int k = 0; k < 128; k++) acc += ctx[k] * W1[(144 + k) * 128 + t];
    d_D[g * 128 + t] = acc;
}

// ------ k_AB: smem-tiled GEMM [40000x64] @ [64x256] -> fp16 A||B --------------
__global__ void k_AB(const float* __restrict__ W1)
{
    __shared__ float sW[32 * 256];       // 32 KB
    __shared__ float sE[32 * 64];        // 8 KB
    int t = threadIdx.x;
    int n0 = blockIdx.x * 32;
    for (int i = t; i < 32 * 64; i += 256) sE[i] = d_emb[(size_t)n0 * 64 + i];
    int tx = t & 31, ty = t >> 5;        // tx: 8-output group, ty: 4-node group
    float acc[4][8];
    #pragma unroll
    for (int j = 0; j < 4; j++)
        #pragma unroll
        for (int o = 0; o < 8; o++) acc[j][o] = 0.f;

    for (int kk = 0; kk < 64; kk += 32) {
        __syncthreads();
        for (int i = t; i < 32 * 256; i += 256) {
            int r = i >> 8, o = i & 255;
            sW[i] = (o < 128) ? W1[(kk + r) * 128 + o]
                              : W1[(64 + kk + r) * 128 + (o - 128)];
        }
        __syncthreads();
        #pragma unroll 4
        for (int r = 0; r < 32; r++) {
            float e0 = sE[(ty * 4 + 0) * 64 + kk + r];
            float e1 = sE[(ty * 4 + 1) * 64 + kk + r];
            float e2 = sE[(ty * 4 + 2) * 64 + kk + r];
            float e3 = sE[(ty * 4 + 3) * 64 + kk + r];
            float4 wa = *(const float4*)(sW + r * 256 + tx * 8);
            float4 wb = *(const float4*)(sW + r * 256 + tx * 8 + 4);
            const float w[8] = {wa.x, wa.y, wa.z, wa.w, wb.x, wb.y, wb.z, wb.w};
            #pragma unroll
            for (int o = 0; o < 8; o++) {
                acc[0][o] += e0 * w[o];
                acc[1][o] += e1 * w[o];
                acc[2][o] += e2 * w[o];
                acc[3][o] += e3 * w[o];
            }
        }
    }
    #pragma unroll
    for (int j = 0; j < 4; j++) {
        int n = n0 + ty * 4 + j;
        int o0 = tx * 8;
        __half2 h[4];
        #pragma unroll
        for (int p = 0; p < 4; p++) h[p] = __floats2half2_rn(acc[j][2 * p], acc[j][2 * p + 1]);
        uint4 u = *(uint4*)h;
        if (o0 < 128) *(uint4*)(d_A + (size_t)n * 128 + o0) = u;
        else          *(uint4*)(d_Bm + (size_t)n * 128 + (o0 - 128)) = u;
    }
}

// ------ final fused edge MLP: CSR per dst node, 2 edges/iter ------------------
__global__ void k_final(const float* __restrict__ W1, const float* __restrict__ W2,
                        const float* __restrict__ b2, float* __restrict__ out)
{
    __shared__ __align__(16) float sW[16 * 128];
    __shared__ float sV[128];
    int t = threadIdx.x;
    for (int i = t; i < 16 * 128; i += 256)
        sW[i] = W1[(128 + (i >> 7)) * 128 + (i & 127)];
    if (t < 128) sV[t] = W2[t];
    __syncthreads();

    int warp = t >> 5, lane = t & 31;
    int j0 = lane * 4;
    float w2x = sV[j0], w2y = sV[j0 + 1], w2z = sV[j0 + 2], w2w = sV[j0 + 3];
    float bias2 = b2[0];

    for (int n = blockIdx.x * 8 + warp; n < NN; n += gridDim.x * 8) {
        int b = n / NPG, ln = n - b * NPG;
        int beg = d_beg[ln], deg = d_cnt[ln];
        if (deg == 0) continue;
        size_t ebase = (size_t)b * EPG + beg;

        uint2 ub = *(const uint2*)(d_Bm + (size_t)n * 128 + j0);
        float2 blo = __half22float2(*(__half2*)&ub.x);
        float2 bhi = __half22float2(*(__half2*)&ub.y);
        float4 vd = *(const float4*)(d_D + b * 128 + j0);
        float4 base;
        base.x = blo.x + vd.x; base.y = blo.y + vd.y;
        base.z = bhi.x + vd.z; base.w = bhi.y + vd.w;

        for (int i = 0; i < deg; i += 2) {
            bool two = (i + 1 < deg);
            int p0 = beg + i, p1 = two ? p0 + 1 : p0;
            int s0 = b * NPG + d_srcp[p0];
            int s1 = b * NPG + d_srcp[p1];

            float efv = __half2float(d_nefp[(ebase + i) * 16 + lane]);

            uint2 ua0 = *(const uint2*)(d_A + (size_t)s0 * 128 + j0);
            uint2 ua1 = *(const uint2*)(d_A + (size_t)s1 * 128 + j0);
            float2 a0lo = __half22float2(*(__half2*)&ua0.x);
            float2 a0hi = __half22float2(*(__half2*)&ua0.y);
            float2 a1lo = __half22float2(*(__half2*)&ua1.x);
            float2 a1hi = __half22float2(*(__half2*)&ua1.y);

            float4 v0, v1;
            v0.x = base.x + a0lo.x; v0.y = base.y + a0lo.y;
            v0.z = base.z + a0hi.x; v0.w = base.w + a0hi.y;
            v1.x = base.x + a1lo.x; v1.y = base.y + a1lo.y;
            v1.z = base.z + a1hi.x; v1.w = base.w + a1hi.y;
            #pragma unroll
            for (int k = 0; k < 16; k++) {
                float ek0 = __shfl_sync(~0u, efv, k);
                float ek1 = __shfl_sync(~0u, efv, 16 + k);
                float4 w = *(const float4*)(sW + k * 128 + j0);
                v0.x += ek0 * w.x; v0.y += ek0 * w.y; v0.z += ek0 * w.z; v0.w += ek0 * w.w;
                v1.x += ek1 * w.x; v1.y += ek1 * w.y; v1.z += ek1 * w.z; v1.w += ek1 * w.w;
            }
            float p0v = fmaxf(v0.x, 0.f) * w2x + fmaxf(v0.y, 0.f) * w2y
                      + fmaxf(v0.z, 0.f) * w2z + fmaxf(v0.w, 0.f) * w2w;
            float p1v = fmaxf(v1.x, 0.f) * w2x + fmaxf(v1.y, 0.f) * w2y
                      + fmaxf(v1.z, 0.f) * w2z + fmaxf(v1.w, 0.f) * w2w;
            #pragma unroll
            for (int o = 16; o; o >>= 1) {
                p0v += __shfl_xor_sync(~0u, p0v, o);
                p1v += __shfl_xor_sync(~0u, p1v, o);
            }
            if (lane == 0) {
                out[(size_t)b * EPG + d_csr[p0]] = p0v + bias2;
                if (two) out[(size_t)b * EPG + d_csr[p1]] = p1v + bias2;
            }
        }
    }
}

// ---------------------------------------------------------------------------
extern "C" void kernel_launch(void* const* d_in, const int* in_sizes, int n_in,
                              void* d_out, int out_size)
{
    const float* node_x    = (const float*)d_in[0];
    const float* edge_attr = (const float*)d_in[1];
    const int*   edge_idx  = (const int*)  d_in[2];
    const float* ln_ng     = (const float*)d_in[3];
    const float* ln_nb     = (const float*)d_in[4];
    const float* ln_eg     = (const float*)d_in[5];
    const float* ln_eb     = (const float*)d_in[6];
    const float* g0_W      = (const float*)d_in[7];
    const float* g0_We     = (const float*)d_in[8];
    const float* g0_asrc   = (const float*)d_in[9];
    const float* g0_adst   = (const float*)d_in[10];
    const float* g0_ae     = (const float*)d_in[11];
    const float* g0_b      = (const float*)d_in[12];
    const float* g1_W      = (const float*)d_in[13];
    const float* g1_We     = (const float*)d_in[14];
    const float* g1_asrc   = (const float*)d_in[15];
    const float* g1_adst   = (const float*)d_in[16];
    const float* g1_ae     = (const float*)d_in[17];
    const float* g1_b      = (const float*)d_in[18];
    const float* mlp_W1    = (const float*)d_in[19];
    const float* mlp_b1    = (const float*)d_in[20];
    const float* mlp_W2    = (const float*)d_in[21];
    const float* mlp_b2    = (const float*)d_in[22];
    float* out = (float*)d_out;

    k_pre<<<40, 256>>>(g0_We, g0_ae, g1_We, g1_ae,
                       g0_W, g0_asrc, g0_adst, g1_W, g1_asrc, g1_adst);
    k_count<<<(EPG + 255) / 256, 256>>>(edge_idx);
    k_assign<<<(NPG + 255) / 256, 256>>>();
    k_scatter<<<(EPG + 255) / 256, 256>>>(edge_idx);
    k_ln_edge<<<GE / 256, 256>>>(edge_attr, ln_eg, ln_eb);
    k_lnproj0<<<NN / 8, 256>>>(node_x, ln_ng, ln_nb, g0_W);
    k_agg0<<<NN / 8, 256>>>(g0_b, g1_W);
    k_agg1<<<NN / 8, 256>>>(g1_b);
    k_D<<<BB, 128>>>(mlp_W1, mlp_b1);
    k_AB<<<NN / 32, 256>>>(mlp_W1);
    k_final<<<1184, 256>>>(mlp_W1, mlp_W2, mlp_b2, out);
}

// round 8
// speedup vs baseline: 2.3574x; 1.2925x over previous
#include <cuda_runtime.h>
#include <cuda_fp16.h>
#include <math.h>

#define BB    8
#define NPG   5000
#define EPG   80000
#define NN    40000
#define GE    640000
#define HID   128
#define EMB   64

// ---------------- scratch (static device arrays) ---------------------------
__device__ int   d_cnt[NPG], d_beg[NPG], d_cur[NPG];
__device__ int   d_csr[EPG + 8];
__device__ int   d_slot[EPG];
__device__ int   d_srcp[EPG + 8];
__device__ int   d_ctr;
__device__ int   d_bar1, d_bar2;
__device__ float d_ee0p[GE], d_ee1p[GE];
__device__ __half d_nefp[GE * 16 + 128];   // padded for quad overread
__device__ __half d_h0[NN * HID];
__device__ float d_s0s[NN], d_s0d[NN];
__device__ __half d_h1[NN * EMB];
__device__ float d_s1s[NN], d_s1d[NN];
__device__ float d_emb[NN * EMB];
__device__ __half d_A[NN * HID], d_Bm[NN * HID];
__device__ float d_D[BB * HID];
__device__ float d_wae0[16], d_wae1[16];
__device__ float d_was0[32], d_wad0[32];
__device__ float d_was1[128], d_wad1[128];
__device__ float d_psum[5000 * 64];
__device__ float d_pmaxf[5000 * 64];
__device__ __half  d_W1hT[256 * 64];       // W1[0:128] packed: [col][k] fp16
__device__ __half2 d_W1ch2[8 * 128];       // W1[128:144] packed half2 pairs over k

// ------------- k_pre: zero counters + precompute packed weights -------------
__global__ void k_pre(const float* __restrict__ We0, const float* __restrict__ ae0,
                      const float* __restrict__ We1, const float* __restrict__ ae1,
                      const float* __restrict__ W0,  const float* __restrict__ as0,
                      const float* __restrict__ ad0, const float* __restrict__ W1g,
                      const float* __restrict__ as1, const float* __restrict__ ad1,
                      const float* __restrict__ mW1)
{
    int t = blockIdx.x * blockDim.x + threadIdx.x;
    int stride = gridDim.x * blockDim.x;
    for (int i = t; i < NPG; i += stride) d_cnt[i] = 0;
    if (t == 0) { d_ctr = 0; d_bar1 = 0; d_bar2 = 0; }
    for (int i = t; i < 256 * 64; i += stride) {
        int col = i >> 6, k = i & 63;
        float w = (col < 128) ? mW1[k * 128 + col] : mW1[(64 + k) * 128 + (col - 128)];
        d_W1hT[i] = __float2half_rn(w);
    }
    for (int i = t; i < 8 * 128; i += stride) {
        int kp = i >> 7, j = i & 127;
        d_W1ch2[i] = __floats2half2_rn(mW1[(128 + 2 * kp) * 128 + j],
                                       mW1[(128 + 2 * kp + 1) * 128 + j]);
    }
    if (blockIdx.x == 0) {
        int tt = threadIdx.x;
        if (tt < 16) {
            float s = 0.f;
            for (int c = 0; c < 128; c++) s += We0[tt * 128 + c] * ae0[c];
            d_wae0[tt] = s;
        } else if (tt < 32) {
            int k = tt - 16;
            float s = 0.f;
            for (int c = 0; c < 64; c++) s += We1[k * 64 + c] * ae1[c];
            d_wae1[k] = s;
        } else if (tt < 64) {
            int k = tt - 32;
            float s0 = 0.f, s1 = 0.f;
            for (int c = 0; c < 128; c++) {
                float w = W0[k * 128 + c];
                s0 += w * as0[c]; s1 += w * ad0[c];
            }
            d_was0[k] = s0; d_wad0[k] = s1;
        }
    } else if (blockIdx.x == 1) {
        int tt = threadIdx.x;
        if (tt < 128) {
            float s0 = 0.f, s1 = 0.f;
            for (int c = 0; c < 64; c++) {
                float w = W1g[tt * 64 + c];
                s0 += w * as1[c]; s1 += w * ad1[c];
            }
            d_was1[tt] = s0; d_wad1[tt] = s1;
        }
    }
}

// ---- CSR build in ONE kernel: count -> assign -> scatter (grid barriers) ---
__device__ __forceinline__ void gbar(int* bar, int target)
{
    __syncthreads();
    if (threadIdx.x == 0) {
        __threadfence();
        atomicAdd(bar, 1);
        while (atomicAdd(bar, 0) < target) { }
    }
    __syncthreads();
}

__global__ void k_csr(const int* __restrict__ ei)
{
    int el = blockIdx.x * 256 + threadIdx.x;
    if (el < EPG) atomicAdd(&d_cnt[ei[EPG + el]], 1);
    gbar(&d_bar1, (int)gridDim.x);
    if (el < NPG) {
        int deg = d_cnt[el];
        int beg = atomicAdd(&d_ctr, deg);
        d_beg[el] = beg;
        d_cur[el] = beg;
    }
    gbar(&d_bar2, (int)gridDim.x);
    if (el < EPG) {
        int dst = ei[EPG + el];
        int pos = atomicAdd(&d_cur[dst], 1);
        d_csr[pos] = el;
        d_slot[el] = pos;
        d_srcp[pos] = ei[el];
    }
}

// ------- fused feature kernel: edge-LN (blocks<2500) + node-LN/proj0 --------
__global__ void k_feat(const float* __restrict__ ea, const float* __restrict__ eg,
                       const float* __restrict__ eb, const float* __restrict__ x,
                       const float* __restrict__ ng, const float* __restrict__ nb,
                       const float* __restrict__ W)
{
    __shared__ float sg[16], sb[16], sw0[16], sw1[16];
    if (blockIdx.x < 2500) {
        if (threadIdx.x < 16) {
            sg[threadIdx.x] = eg[threadIdx.x];
            sb[threadIdx.x] = eb[threadIdx.x];
            sw0[threadIdx.x] = d_wae0[threadIdx.x];
            sw1[threadIdx.x] = d_wae1[threadIdx.x];
        }
        __syncthreads();
        int ge = blockIdx.x * 256 + threadIdx.x;
        int bb = ge / EPG;
        int el = ge - bb * EPG;
        int pos = d_slot[el];
        size_t base = (size_t)bb * EPG + pos;

        const float4* rp = (const float4*)(ea + (size_t)ge * 16);
        float4 q[4];
        q[0] = rp[0]; q[1] = rp[1]; q[2] = rp[2]; q[3] = rp[3];
        float* v = (float*)q;
        float mu = 0.f;
        #pragma unroll
        for (int k = 0; k < 16; k++) mu += v[k];
        mu *= (1.f / 16.f);
        float var = 0.f;
        #pragma unroll
        for (int k = 0; k < 16; k++) { float d = v[k] - mu; var += d * d; }
        var *= (1.f / 16.f);
        float r = rsqrtf(var + 1e-5f);
        float e0 = 0.f, e1 = 0.f;
        __half2 hh[8];
        #pragma unroll
        for (int k = 0; k < 16; k += 2) {
            float y0 = (v[k] - mu) * r * sg[k] + sb[k];
            float y1 = (v[k + 1] - mu) * r * sg[k + 1] + sb[k + 1];
            e0 += y0 * sw0[k] + y1 * sw0[k + 1];
            e1 += y0 * sw1[k] + y1 * sw1[k + 1];
            hh[k >> 1] = __floats2half2_rn(y0, y1);
        }
        uint4* wp = (uint4*)(d_nefp + base * 16);
        wp[0] = *(uint4*)&hh[0];
        wp[1] = *(uint4*)&hh[4];
        d_ee0p[base] = e0;
        d_ee1p[base] = e1;
    } else {
        int warp = threadIdx.x >> 5, lane = threadIdx.x & 31;
        int n = (blockIdx.x - 2500) * 8 + warp;
        float v = x[n * 32 + lane];
        float mu = v;
        #pragma unroll
        for (int o = 16; o; o >>= 1) mu += __shfl_xor_sync(~0u, mu, o);
        mu *= (1.f / 32.f);
        float d = v - mu;
        float var = d * d;
        #pragma unroll
        for (int o = 16; o; o >>= 1) var += __shfl_xor_sync(~0u, var, o);
        var *= (1.f / 32.f);
        float y = d * rsqrtf(var + 1e-5f) * ng[lane] + nb[lane];

        float ps = y * d_was0[lane], pd = y * d_wad0[lane];
        #pragma unroll
        for (int o = 16; o; o >>= 1) {
            ps += __shfl_xor_sync(~0u, ps, o);
            pd += __shfl_xor_sync(~0u, pd, o);
        }
        if (lane == 0) { d_s0s[n] = ps; d_s0d[n] = pd; }

        float a0 = 0.f, a1 = 0.f, a2 = 0.f, a3 = 0.f;
        #pragma unroll 8
        for (int k = 0; k < 32; k++) {
            float yk = __shfl_sync(~0u, y, k);
            float4 w = *(const float4*)(W + k * 128 + lane * 4);
            a0 += yk * w.x; a1 += yk * w.y; a2 += yk * w.z; a3 += yk * w.w;
        }
        __half2 h01 = __floats2half2_rn(a0, a1);
        __half2 h23 = __floats2half2_rn(a2, a3);
        uint2 u; u.x = *(unsigned*)&h01; u.y = *(unsigned*)&h23;
        *(uint2*)(d_h0 + (size_t)n * 128 + lane * 4) = u;
    }
}

// -------- fp16 gather helper -------------------------------------------------
template<int K>
__device__ __forceinline__ void gatherH(float* acc, const __half* __restrict__ h,
                                        int S, float A, int lane)
{
    if constexpr (K == 4) {
        uint2 u = *(const uint2*)(h + (size_t)S * 128 + lane * 4);
        float2 f01 = __half22float2(*(__half2*)&u.x);
        float2 f23 = __half22float2(*(__half2*)&u.y);
        acc[0] += A * f01.x; acc[1] += A * f01.y;
        acc[2] += A * f23.x; acc[3] += A * f23.y;
    } else {
        __half2 hv = *(const __half2*)(h + (size_t)S * 64 + lane * 2);
        float2 f = __half22float2(hv);
        acc[0] += A * f.x; acc[1] += A * f.y;
    }
}

// -------- shared softmax+gather core ------------------------------------------
template<int K>
__device__ __forceinline__ void agg_core(float* acc, const __half* __restrict__ h,
                                         const float* __restrict__ ss,
                                         const float* __restrict__ eep,
                                         float sdv, int b, int beg, int deg,
                                         size_t ebase, int lane)
{
    if (deg <= 32) {
        int src = 0;
        float lg = -1e30f;
        if (lane < deg) {
            int sl = d_srcp[beg + lane];
            src = b * NPG + sl;
            lg = ss[src] + sdv + eep[ebase + lane];
            lg = lg > 0.f ? lg : 0.2f * lg;
        }
        float M = lg;
        #pragma unroll
        for (int o = 16; o; o >>= 1) M = fmaxf(M, __shfl_xor_sync(~0u, M, o));
        float ex = (lane < deg) ? __expf(lg - M) : 0.f;
        float sm = ex;
        #pragma unroll
        for (int o = 16; o; o >>= 1) sm += __shfl_xor_sync(~0u, sm, o);
        float alpha = ex / (sm + 1e-16f);
        for (int j = 0; j < deg; j += 8) {
            #pragma unroll
            for (int q = 0; q < 8; q++) {
                float A = __shfl_sync(~0u, alpha, j + q);
                int S   = __shfl_sync(~0u, src, j + q);
                gatherH<K>(acc, h, S, A, lane);
            }
        }
    } else {
        float m = -1e30f, sm = 0.f;
        for (int i = lane; i < deg; i += 32) {
            int sl = d_srcp[beg + i];
            float lg = ss[b * NPG + sl] + sdv + eep[ebase + i];
            lg = lg > 0.f ? lg : 0.2f * lg;
            float nm = fmaxf(m, lg);
            sm = sm * __expf(m - nm) + __expf(lg - nm);
            m = nm;
        }
        float M = m;
        #pragma unroll
        for (int o = 16; o; o >>= 1) M = fmaxf(M, __shfl_xor_sync(~0u, M, o));
        sm *= __expf(m - M);
        #pragma unroll
        for (int o = 16; o; o >>= 1) sm += __shfl_xor_sync(~0u, sm, o);
        float inv = 1.f / (sm + 1e-16f);
        for (int basei = 0; basei < deg; basei += 32) {
            int i = basei + lane;
            float alpha = 0.f;
            int src = 0;
            if (i < deg) {
                int sl = d_srcp[beg + i];
                src = b * NPG + sl;
                float lg = ss[src] + sdv + eep[ebase + i];
                lg = lg > 0.f ? lg : 0.2f * lg;
                alpha = __expf(lg - M) * inv;
            }
            int cnt = min(32, deg - basei);
            for (int j = 0; j < cnt; j += 8) {
                #pragma unroll
                for (int q = 0; q < 8; q++) {
                    float A = __shfl_sync(~0u, alpha, j + q);
                    int S   = __shfl_sync(~0u, src, j + q);
                    gatherH<K>(acc, h, S, A, lane);
                }
            }
        }
    }
}

// -------- agg0 fused with proj1 ------------------------------------------------
__global__ void k_agg0(const float* __restrict__ bias, const float* __restrict__ W1g)
{
    __shared__ float sg0[8][128];
    int warp = threadIdx.x >> 5, lane = threadIdx.x & 31;
    int n = blockIdx.x * 8 + warp;
    int b = n / NPG, ln = n - b * NPG;
    int beg = d_beg[ln], deg = d_cnt[ln];
    size_t ebase = (size_t)b * EPG + beg;
    float acc[4] = {0.f, 0.f, 0.f, 0.f};
    if (deg > 0)
        agg_core<4>(acc, d_h0, d_s0s, d_ee0p, d_s0d[n], b, beg, deg, ebase, lane);

    float ps = 0.f, pd = 0.f;
    #pragma unroll
    for (int u = 0; u < 4; u++) {
        float t = acc[u] + bias[lane * 4 + u];
        t = t > 0.f ? t : expm1f(t);
        sg0[warp][lane * 4 + u] = t;
        ps += t * d_was1[lane * 4 + u];
        pd += t * d_wad1[lane * 4 + u];
    }
    #pragma unroll
    for (int o = 16; o; o >>= 1) {
        ps += __shfl_xor_sync(~0u, ps, o);
        pd += __shfl_xor_sync(~0u, pd, o);
    }
    if (lane == 0) { d_s1s[n] = ps; d_s1d[n] = pd; }
    __syncwarp();

    float a0 = 0.f, a1 = 0.f;
    const float* row = sg0[warp];
    #pragma unroll 4
    for (int k = 0; k < 128; k++) {
        float gv = row[k];
        float2 w = *(const float2*)(W1g + k * 64 + lane * 2);
        a0 += gv * w.x; a1 += gv * w.y;
    }
    __half2 hh = __floats2half2_rn(a0, a1);
    *(__half2*)(d_h1 + (size_t)n * 64 + lane * 2) = hh;
}

// -------- agg1 fused with pooling partials --------------------------------------
__global__ void k_agg1(const float* __restrict__ bias)
{
    __shared__ float semb[8][64];
    int warp = threadIdx.x >> 5, lane = threadIdx.x & 31;
    int n = blockIdx.x * 8 + warp;
    int b = n / NPG, ln = n - b * NPG;
    int beg = d_beg[ln], deg = d_cnt[ln];
    size_t ebase = (size_t)b * EPG + beg;
    float acc[2] = {0.f, 0.f};
    if (deg > 0)
        agg_core<2>(acc, d_h1, d_s1s, d_ee1p, d_s1d[n], b, beg, deg, ebase, lane);

    float v0 = acc[0] + bias[lane * 2];
    float v1 = acc[1] + bias[lane * 2 + 1];
    float2 f2; f2.x = v0; f2.y = v1;
    *(float2*)(d_emb + (size_t)n * 64 + lane * 2) = f2;
    semb[warp][lane * 2] = v0;
    semb[warp][lane * 2 + 1] = v1;
    __syncthreads();
    int t = threadIdx.x;
    if (t < 64) {
        float s = 0.f, m = -1e30f;
        #pragma unroll
        for (int r = 0; r < 8; r++) {
            float x = semb[r][t];
            s += x; m = fmaxf(m, x);
        }
        d_psum[blockIdx.x * 64 + t] = s;
        d_pmaxf[blockIdx.x * 64 + t] = m;
    }
}

// ------ k_D: hierarchical pooling reduce + ctx GEMM (8 blocks x 1024) --------
__global__ void k_D(const float* __restrict__ W1, const float* __restrict__ b1)
{
    __shared__ float red[1024];
    __shared__ float ctx[128];
    int g = blockIdx.x;
    int t = threadIdx.x;
    int c = t & 63, r = t >> 6;
    float s = 0.f, m = -1e30f;
    for (int i = r; i < 625; i += 16) {
        int idx = (g * 625 + i) * 64 + c;
        s += d_psum[idx];
        m = fmaxf(m, d_pmaxf[idx]);
    }
    red[t] = s;
    __syncthreads();
    for (int rr = 8; rr >= 1; rr >>= 1) {
        if (r < rr) red[t] += red[t + rr * 64];
        __syncthreads();
    }
    if (r == 0) ctx[c] = red[c] * (1.f / NPG);
    __syncthreads();
    red[t] = m;
    __syncthreads();
    for (int rr = 8; rr >= 1; rr >>= 1) {
        if (r < rr) red[t] = fmaxf(red[t], red[t + rr * 64]);
        __syncthreads();
    }
    if (r == 0) ctx[64 + c] = red[c];
    __syncthreads();
    int c2 = t & 127, p = t >> 7;
    float acc = 0.f;
    #pragma unroll
    for (int k = p * 16; k < p * 16 + 16; k++)
        acc += ctx[k] * W1[(144 + k) * 128 + c2];
    red[t] = acc;
    __syncthreads();
    if (p == 0) {
        float tot = b1[c2];
        #pragma unroll
        for (int q = 0; q < 8; q++) tot += red[q * 128 + c2];
        d_D[g * 128 + c2] = tot;
    }
}

// ------ k_AB: tensor-core GEMM emb[40000x64] @ W1hT -> A||B (fp16) -----------
__global__ void k_AB()
{
    __shared__ __half sW[256 * 64];      // 32 KB, [col][k]
    __shared__ __half sE[32 * 64];       // 4 KB,  [node][k]
    int t = threadIdx.x;
    int n0 = blockIdx.x * 32;
    {
        const uint4* src = (const uint4*)d_W1hT;
        uint4* dst = (uint4*)sW;
        for (int i = t; i < 256 * 64 / 8; i += 256) dst[i] = src[i];
    }
    {
        const float2* src = (const float2*)(d_emb + (size_t)n0 * 64);
        __half2* dst = (__half2*)sE;
        for (int i = t; i < 32 * 64 / 2; i += 256) {
            float2 f = src[i];
            dst[i] = __floats2half2_rn(f.x, f.y);
        }
    }
    __syncthreads();

    int warp = t >> 5, lane = t & 31;
    int s = warp & 1;
    int g = warp >> 1;
    int gr = lane >> 2, tc = lane & 3;

    float acc[8][4];
    #pragma unroll
    for (int tt = 0; tt < 8; tt++)
        #pragma unroll
        for (int u = 0; u < 4; u++) acc[tt][u] = 0.f;

    #pragma unroll
    for (int kk = 0; kk < 64; kk += 16) {
        unsigned a0 = *(const unsigned*)(sE + (s * 16 + gr) * 64 + kk + 2 * tc);
        unsigned a1 = *(const unsigned*)(sE + (s * 16 + gr + 8) * 64 + kk + 2 * tc);
        unsigned a2 = *(const unsigned*)(sE + (s * 16 + gr) * 64 + kk + 2 * tc + 8);
        unsigned a3 = *(const unsigned*)(sE + (s * 16 + gr + 8) * 64 + kk + 2 * tc + 8);
        #pragma unroll
        for (int tt = 0; tt < 8; tt++) {
            int col = g * 64 + tt * 8 + (lane >> 2);
            unsigned b0 = *(const unsigned*)(sW + col * 64 + kk + 2 * tc);
            unsigned b1 = *(const unsigned*)(sW + col * 64 + kk + 2 * tc + 8);
            asm volatile(
                "mma.sync.aligned.m16n8k16.row.col.f32.f16.f16.f32 "
                "{%0,%1,%2,%3},{%4,%5,%6,%7},{%8,%9},{%0,%1,%2,%3};"
                : "+f"(acc[tt][0]), "+f"(acc[tt][1]), "+f"(acc[tt][2]), "+f"(acc[tt][3])
                : "r"(a0), "r"(a1), "r"(a2), "r"(a3), "r"(b0), "r"(b1));
        }
    }
    #pragma unroll
    for (int tt = 0; tt < 8; tt++) {
        int c = g * 64 + tt * 8 + 2 * tc;
        int r0 = n0 + s * 16 + gr, r1 = r0 + 8;
        __half2 h0 = __floats2half2_rn(acc[tt][0], acc[tt][1]);
        __half2 h1 = __floats2half2_rn(acc[tt][2], acc[tt][3]);
        if (c < 128) {
            *(__half2*)(d_A + (size_t)r0 * 128 + c) = h0;
            *(__half2*)(d_A + (size_t)r1 * 128 + c) = h1;
        } else {
            *(__half2*)(d_Bm + (size_t)r0 * 128 + c - 128) = h0;
            *(__half2*)(d_Bm + (size_t)r1 * 128 + c - 128) = h1;
        }
    }
}

// ------ final fused edge MLP: per dst node, 4 edges/iter, HFMA2 k-loop --------
__global__ void k_final(const float* __restrict__ W2, const float* __restrict__ b2,
                        float* __restrict__ out)
{
    __shared__ __align__(16) __half2 sW[8 * 128];   // 4096 bytes = 256 uint4
    __shared__ float sV[128];
    int t = threadIdx.x;
    {
        const uint4* src = (const uint4*)d_W1ch2;
        uint4* dst = (uint4*)sW;
        for (int i = t; i < 256; i += 256) dst[i] = src[i];   // FIXED bound
    }
    if (t < 128) sV[t] = W2[t];
    __syncthreads();

    int warp = t >> 5, lane = t & 31;
    int j0 = lane * 4;
    float w2x = sV[j0], w2y = sV[j0 + 1], w2z = sV[j0 + 2], w2w = sV[j0 + 3];
    float bias2 = b2[0];
    int myedge = lane >> 3;
    int mykp = lane & 7;

    for (int n = blockIdx.x * 8 + warp; n < NN; n += gridDim.x * 8) {
        int b = n / NPG, ln = n - b * NPG;
        int beg = d_beg[ln], deg = d_cnt[ln];
        if (deg == 0) continue;
        size_t ebase = (size_t)b * EPG + beg;

        uint2 ub = *(const uint2*)(d_Bm + (size_t)n * 128 + j0);
        float2 blo = __half22float2(*(__half2*)&ub.x);
        float2 bhi = __half22float2(*(__half2*)&ub.y);
        float4 vd = *(const float4*)(d_D + b * 128 + j0);
        float4 base;
        base.x = blo.x + vd.x; base.y = blo.y + vd.y;
        base.z = bhi.x + vd.z; base.w = bhi.y + vd.w;

        for (int i = 0; i < deg; i += 4) {
            unsigned efu = *(const unsigned*)(d_nefp + (ebase + i + myedge) * 16 + mykp * 2);

            int p0 = beg + min(i + 0, deg - 1);
            int p1 = beg + min(i + 1, deg - 1);
            int p2 = beg + min(i + 2, deg - 1);
            int p3 = beg + min(i + 3, deg - 1);
            int s0 = b * NPG + d_srcp[p0];
            int s1 = b * NPG + d_srcp[p1];
            int s2 = b * NPG + d_srcp[p2];
            int s3 = b * NPG + d_srcp[p3];
            uint2 ua0 = *(const uint2*)(d_A + (size_t)s0 * 128 + j0);
            uint2 ua1 = *(const uint2*)(d_A + (size_t)s1 * 128 + j0);
            uint2 ua2 = *(const uint2*)(d_A + (size_t)s2 * 128 + j0);
            uint2 ua3 = *(const uint2*)(d_A + (size_t)s3 * 128 + j0);

            __half2 acc0[4], acc1[4], acc2[4], acc3[4];
            #pragma unroll
            for (int u = 0; u < 4; u++)
                acc0[u] = acc1[u] = acc2[u] = acc3[u] = __floats2half2_rn(0.f, 0.f);

            #pragma unroll
            for (int kp = 0; kp < 8; kp++) {
                uint4 wq = *(const uint4*)(sW + kp * 128 + j0);
                const __half2* w2 = (const __half2*)&wq;
                unsigned e0u = __shfl_sync(~0u, efu, 0 * 8 + kp);
                unsigned e1u = __shfl_sync(~0u, efu, 1 * 8 + kp);
                unsigned e2u = __shfl_sync(~0u, efu, 2 * 8 + kp);
                unsigned e3u = __shfl_sync(~0u, efu, 3 * 8 + kp);
                __half2 e0 = *(__half2*)&e0u, e1 = *(__half2*)&e1u;
                __half2 e2 = *(__half2*)&e2u, e3 = *(__half2*)&e3u;
                #pragma unroll
                for (int u = 0; u < 4; u++) {
                    acc0[u] = __hfma2(e0, w2[u], acc0[u]);
                    acc1[u] = __hfma2(e1, w2[u], acc1[u]);
                    acc2[u] = __hfma2(e2, w2[u], acc2[u]);
                    acc3[u] = __hfma2(e3, w2[u], acc3[u]);
                }
            }

            float p[4];
            uint2 uas[4] = {ua0, ua1, ua2, ua3};
            __half2* accs[4] = {acc0, acc1, acc2, acc3};
            #pragma unroll
            for (int e = 0; e < 4; e++) {
                float2 alo = __half22float2(*(__half2*)&uas[e].x);
                float2 ahi = __half22float2(*(__half2*)&uas[e].y);
                float2 c0 = __half22float2(accs[e][0]);
                float2 c1 = __half22float2(accs[e][1]);
                float2 c2 = __half22float2(accs[e][2]);
                float2 c3 = __half22float2(accs[e][3]);
                float vx = base.x + alo.x + c0.x + c0.y;
                float vy = base.y + alo.y + c1.x + c1.y;
                float vz = base.z + ahi.x + c2.x + c2.y;
                float vw = base.w + ahi.y + c3.x + c3.y;
                float pv = fmaxf(vx, 0.f) * w2x + fmaxf(vy, 0.f) * w2y
                         + fmaxf(vz, 0.f) * w2z + fmaxf(vw, 0.f) * w2w;
                #pragma unroll
                for (int o = 16; o; o >>= 1) pv += __shfl_xor_sync(~0u, pv, o);
                p[e] = pv;
            }
            if (lane == 0) {
                out[(size_t)b * EPG + d_csr[p0]] = p[0] + bias2;
                if (i + 1 < deg) out[(size_t)b * EPG + d_csr[p1]] = p[1] + bias2;
                if (i + 2 < deg) out[(size_t)b * EPG + d_csr[p2]] = p[2] + bias2;
                if (i + 3 < deg) out[(size_t)b * EPG + d_csr[p3]] = p[3] + bias2;
            }
        }
    }
}

// ---------------------------------------------------------------------------
extern "C" void kernel_launch(void* const* d_in, const int* in_sizes, int n_in,
                              void* d_out, int out_size)
{
    const float* node_x    = (const float*)d_in[0];
    const float* edge_attr = (const float*)d_in[1];
    const int*   edge_idx  = (const int*)  d_in[2];
    const float* ln_ng     = (const float*)d_in[3];
    const float* ln_nb     = (const float*)d_in[4];
    const float* ln_eg     = (const float*)d_in[5];
    const float* ln_eb     = (const float*)d_in[6];
    const float* g0_W      = (const float*)d_in[7];
    const float* g0_We     = (const float*)d_in[8];
    const float* g0_asrc   = (const float*)d_in[9];
    const float* g0_adst   = (const float*)d_in[10];
    const float* g0_ae     = (const float*)d_in[11];
    const float* g0_b      = (const float*)d_in[12];
    const float* g1_W      = (const float*)d_in[13];
    const float* g1_We     = (const float*)d_in[14];
    const float* g1_asrc   = (const float*)d_in[15];
    const float* g1_adst   = (const float*)d_in[16];
    const float* g1_ae     = (const float*)d_in[17];
    const float* g1_b      = (const float*)d_in[18];
    const float* mlp_W1    = (const float*)d_in[19];
    const float* mlp_b1    = (const float*)d_in[20];
    const float* mlp_W2    = (const float*)d_in[21];
    const float* mlp_b2    = (const float*)d_in[22];
    float* out = (float*)d_out;

    k_pre<<<40, 256>>>(g0_We, g0_ae, g1_We, g1_ae,
                       g0_W, g0_asrc, g0_adst, g1_W, g1_asrc, g1_adst, mlp_W1);
    k_csr<<<313, 256>>>(edge_idx);
    k_feat<<<7500, 256>>>(edge_attr, ln_eg, ln_eb, node_x, ln_ng, ln_nb, g0_W);
    k_agg0<<<5000, 256>>>(g0_b, g1_W);      // <- profiled launch slot
    k_agg1<<<5000, 256>>>(g1_b);
    k_D<<<BB, 1024>>>(mlp_W1, mlp_b1);
    k_AB<<<NN / 32, 256>>>();
    k_final<<<1184, 256>>>(mlp_W2, mlp_b2, out);
}

// round 9
// speedup vs baseline: 3.2202x; 1.3660x over previous
#include <cuda_runtime.h>
#include <cuda_fp16.h>
#include <math.h>

#define BB    8
#define NPG   5000
#define EPG   80000
#define NN    40000
#define GE    640000
#define HID   128
#define EMB   64

#define MMA_FP16(acc, a0, a1, a2, a3, b0, b1)                                   \
    asm volatile(                                                               \
        "mma.sync.aligned.m16n8k16.row.col.f32.f16.f16.f32 "                    \
        "{%0,%1,%2,%3},{%4,%5,%6,%7},{%8,%9},{%0,%1,%2,%3};"                    \
        : "+f"(acc[0]), "+f"(acc[1]), "+f"(acc[2]), "+f"(acc[3])                \
        : "r"(a0), "r"(a1), "r"(a2), "r"(a3), "r"(b0), "r"(b1))

// ---------------- scratch (static device arrays) ---------------------------
__device__ int   d_cnt[NPG], d_beg[NPG], d_cur[NPG];
__device__ int   d_csr[EPG + 16];
__device__ int   d_slot[EPG];
__device__ int   d_srcp[EPG + 16];
__device__ int   d_ctr;
__device__ int   d_bar1, d_bar2;
__device__ float d_ee0p[GE], d_ee1p[GE];
__device__ __half d_nefp[GE * 16 + 256];   // padded: k_final tiles may overread 15 rows
__device__ __half d_h0[NN * HID];
__device__ float d_s0s[NN], d_s0d[NN];
__device__ __half d_g0h[NN * HID];         // fp16 g0 (input to proj1 mma)
__device__ __half d_h1[NN * EMB];
__device__ float d_s1s[NN], d_s1d[NN];
__device__ float d_emb[NN * EMB];
__device__ __half d_A[NN * HID], d_Bm[NN * HID];
__device__ float d_D[BB * HID];
__device__ float d_wae0[16], d_wae1[16];
__device__ float d_was0[32], d_wad0[32];
__device__ float d_was1[128], d_wad1[128];
__device__ float d_psum[5000 * 64];
__device__ float d_pmaxf[5000 * 64];
__device__ __half  d_W1hT[256 * 64];       // W1[0:128] packed [col][k] fp16 (k_AB)
__device__ __half  d_W1gT[64 * 128];       // gat1_W packed [col][k] fp16 (proj1 mma)
__device__ unsigned d_WBf[16 * 2 * 32];    // W1c mma B-fragments: [nt][reg][lane]

// ------------- k_pre: zero counters + precompute packed weights -------------
__global__ void k_pre(const float* __restrict__ We0, const float* __restrict__ ae0,
                      const float* __restrict__ We1, const float* __restrict__ ae1,
                      const float* __restrict__ W0,  const float* __restrict__ as0,
                      const float* __restrict__ ad0, const float* __restrict__ W1g,
                      const float* __restrict__ as1, const float* __restrict__ ad1,
                      const float* __restrict__ mW1)
{
    int t = blockIdx.x * blockDim.x + threadIdx.x;
    int stride = gridDim.x * blockDim.x;
    for (int i = t; i < NPG; i += stride) d_cnt[i] = 0;
    if (t == 0) { d_ctr = 0; d_bar1 = 0; d_bar2 = 0; }
    for (int i = t; i < 256 * 64; i += stride) {
        int col = i >> 6, k = i & 63;
        float w = (col < 128) ? mW1[k * 128 + col] : mW1[(64 + k) * 128 + (col - 128)];
        d_W1hT[i] = __float2half_rn(w);
    }
    for (int i = t; i < 64 * 128; i += stride) {
        int col = i >> 7, k = i & 127;
        d_W1gT[i] = __float2half_rn(W1g[k * 64 + col]);
    }
    // W1c mma B fragments: nt in 0..15, r in 0..1, lane in 0..31
    for (int i = t; i < 1024; i += stride) {
        int q = i >> 5, L = i & 31;
        int nt = q >> 1, r = q & 1;
        int gr = L >> 2, tc = L & 3;
        int k0 = 2 * tc + 8 * r;
        int j  = nt * 8 + gr;
        __half2 h = __floats2half2_rn(mW1[(128 + k0) * 128 + j],
                                      mW1[(128 + k0 + 1) * 128 + j]);
        d_WBf[i] = *(unsigned*)&h;
    }
    if (blockIdx.x == 0) {
        int tt = threadIdx.x;
        if (tt < 16) {
            float s = 0.f;
            for (int c = 0; c < 128; c++) s += We0[tt * 128 + c] * ae0[c];
            d_wae0[tt] = s;
        } else if (tt < 32) {
            int k = tt - 16;
            float s = 0.f;
            for (int c = 0; c < 64; c++) s += We1[k * 64 + c] * ae1[c];
            d_wae1[k] = s;
        } else if (tt < 64) {
            int k = tt - 32;
            float s0 = 0.f, s1 = 0.f;
            for (int c = 0; c < 128; c++) {
                float w = W0[k * 128 + c];
                s0 += w * as0[c]; s1 += w * ad0[c];
            }
            d_was0[k] = s0; d_wad0[k] = s1;
        }
    } else if (blockIdx.x == 1) {
        int tt = threadIdx.x;
        if (tt < 128) {
            float s0 = 0.f, s1 = 0.f;
            for (int c = 0; c < 64; c++) {
                float w = W1g[tt * 64 + c];
                s0 += w * as1[c]; s1 += w * ad1[c];
            }
            d_was1[tt] = s0; d_wad1[tt] = s1;
        }
    }
}

// ---- CSR build in ONE kernel: count -> assign -> scatter (grid barriers) ---
__device__ __forceinline__ void gbar(int* bar, int target)
{
    __syncthreads();
    if (threadIdx.x == 0) {
        __threadfence();
        atomicAdd(bar, 1);
        while (atomicAdd(bar, 0) < target) { }
    }
    __syncthreads();
}

__global__ void k_csr(const int* __restrict__ ei)
{
    int el = blockIdx.x * 256 + threadIdx.x;
    if (el < EPG) atomicAdd(&d_cnt[ei[EPG + el]], 1);
    gbar(&d_bar1, (int)gridDim.x);
    if (el < NPG) {
        int deg = d_cnt[el];
        int beg = atomicAdd(&d_ctr, deg);
        d_beg[el] = beg;
        d_cur[el] = beg;
    }
    gbar(&d_bar2, (int)gridDim.x);
    if (el < EPG) {
        int dst = ei[EPG + el];
        int pos = atomicAdd(&d_cur[dst], 1);
        d_csr[pos] = el;
        d_slot[el] = pos;
        d_srcp[pos] = ei[el];
    }
}

// ------- fused feature kernel: edge-LN (blocks<2500) + node-LN/proj0 --------
__global__ void k_feat(const float* __restrict__ ea, const float* __restrict__ eg,
                       const float* __restrict__ eb, const float* __restrict__ x,
                       const float* __restrict__ ng, const float* __restrict__ nb,
                       const float* __restrict__ W)
{
    __shared__ float sg[16], sb[16], sw0[16], sw1[16];
    if (blockIdx.x < 2500) {
        if (threadIdx.x < 16) {
            sg[threadIdx.x] = eg[threadIdx.x];
            sb[threadIdx.x] = eb[threadIdx.x];
            sw0[threadIdx.x] = d_wae0[threadIdx.x];
            sw1[threadIdx.x] = d_wae1[threadIdx.x];
        }
        __syncthreads();
        int ge = blockIdx.x * 256 + threadIdx.x;
        int bb = ge / EPG;
        int el = ge - bb * EPG;
        int pos = d_slot[el];
        size_t base = (size_t)bb * EPG + pos;

        const float4* rp = (const float4*)(ea + (size_t)ge * 16);
        float4 q[4];
        q[0] = rp[0]; q[1] = rp[1]; q[2] = rp[2]; q[3] = rp[3];
        float* v = (float*)q;
        float mu = 0.f;
        #pragma unroll
        for (int k = 0; k < 16; k++) mu += v[k];
        mu *= (1.f / 16.f);
        float var = 0.f;
        #pragma unroll
        for (int k = 0; k < 16; k++) { float d = v[k] - mu; var += d * d; }
        var *= (1.f / 16.f);
        float r = rsqrtf(var + 1e-5f);
        float e0 = 0.f, e1 = 0.f;
        __half2 hh[8];
        #pragma unroll
        for (int k = 0; k < 16; k += 2) {
            float y0 = (v[k] - mu) * r * sg[k] + sb[k];
            float y1 = (v[k + 1] - mu) * r * sg[k + 1] + sb[k + 1];
            e0 += y0 * sw0[k] + y1 * sw0[k + 1];
            e1 += y0 * sw1[k] + y1 * sw1[k + 1];
            hh[k >> 1] = __floats2half2_rn(y0, y1);
        }
        uint4* wp = (uint4*)(d_nefp + base * 16);
        wp[0] = *(uint4*)&hh[0];
        wp[1] = *(uint4*)&hh[4];
        d_ee0p[base] = e0;
        d_ee1p[base] = e1;
    } else {
        int warp = threadIdx.x >> 5, lane = threadIdx.x & 31;
        int n = (blockIdx.x - 2500) * 8 + warp;
        float v = x[n * 32 + lane];
        float mu = v;
        #pragma unroll
        for (int o = 16; o; o >>= 1) mu += __shfl_xor_sync(~0u, mu, o);
        mu *= (1.f / 32.f);
        float d = v - mu;
        float var = d * d;
        #pragma unroll
        for (int o = 16; o; o >>= 1) var += __shfl_xor_sync(~0u, var, o);
        var *= (1.f / 32.f);
        float y = d * rsqrtf(var + 1e-5f) * ng[lane] + nb[lane];

        float ps = y * d_was0[lane], pd = y * d_wad0[lane];
        #pragma unroll
        for (int o = 16; o; o >>= 1) {
            ps += __shfl_xor_sync(~0u, ps, o);
            pd += __shfl_xor_sync(~0u, pd, o);
        }
        if (lane == 0) { d_s0s[n] = ps; d_s0d[n] = pd; }

        float a0 = 0.f, a1 = 0.f, a2 = 0.f, a3 = 0.f;
        #pragma unroll 8
        for (int k = 0; k < 32; k++) {
            float yk = __shfl_sync(~0u, y, k);
            float4 w = *(const float4*)(W + k * 128 + lane * 4);
            a0 += yk * w.x; a1 += yk * w.y; a2 += yk * w.z; a3 += yk * w.w;
        }
        __half2 h01 = __floats2half2_rn(a0, a1);
        __half2 h23 = __floats2half2_rn(a2, a3);
        uint2 u; u.x = *(unsigned*)&h01; u.y = *(unsigned*)&h23;
        *(uint2*)(d_h0 + (size_t)n * 128 + lane * 4) = u;
    }
}

// -------- fp16 gather helper -------------------------------------------------
template<int K>
__device__ __forceinline__ void gatherH(float* acc, const __half* __restrict__ h,
                                        int S, float A, int lane)
{
    if constexpr (K == 4) {
        uint2 u = *(const uint2*)(h + (size_t)S * 128 + lane * 4);
        float2 f01 = __half22float2(*(__half2*)&u.x);
        float2 f23 = __half22float2(*(__half2*)&u.y);
        acc[0] += A * f01.x; acc[1] += A * f01.y;
        acc[2] += A * f23.x; acc[3] += A * f23.y;
    } else {
        __half2 hv = *(const __half2*)(h + (size_t)S * 64 + lane * 2);
        float2 f = __half22float2(hv);
        acc[0] += A * f.x; acc[1] += A * f.y;
    }
}

// -------- shared softmax+gather core ------------------------------------------
template<int K>
__device__ __forceinline__ void agg_core(float* acc, const __half* __restrict__ h,
                                         const float* __restrict__ ss,
                                         const float* __restrict__ eep,
                                         float sdv, int b, int beg, int deg,
                                         size_t ebase, int lane)
{
    if (deg <= 32) {
        int src = 0;
        float lg = -1e30f;
        if (lane < deg) {
            int sl = d_srcp[beg + lane];
            src = b * NPG + sl;
            lg = ss[src] + sdv + eep[ebase + lane];
            lg = lg > 0.f ? lg : 0.2f * lg;
        }
        float M = lg;
        #pragma unroll
        for (int o = 16; o; o >>= 1) M = fmaxf(M, __shfl_xor_sync(~0u, M, o));
        float ex = (lane < deg) ? __expf(lg - M) : 0.f;
        float sm = ex;
        #pragma unroll
        for (int o = 16; o; o >>= 1) sm += __shfl_xor_sync(~0u, sm, o);
        float alpha = ex / (sm + 1e-16f);
        for (int j = 0; j < deg; j += 8) {
            #pragma unroll
            for (int q = 0; q < 8; q++) {
                float A = __shfl_sync(~0u, alpha, j + q);
                int S   = __shfl_sync(~0u, src, j + q);
                gatherH<K>(acc, h, S, A, lane);
            }
        }
    } else {
        float m = -1e30f, sm = 0.f;
        for (int i = lane; i < deg; i += 32) {
            int sl = d_srcp[beg + i];
            float lg = ss[b * NPG + sl] + sdv + eep[ebase + i];
            lg = lg > 0.f ? lg : 0.2f * lg;
            float nm = fmaxf(m, lg);
            sm = sm * __expf(m - nm) + __expf(lg - nm);
            m = nm;
        }
        float M = m;
        #pragma unroll
        for (int o = 16; o; o >>= 1) M = fmaxf(M, __shfl_xor_sync(~0u, M, o));
        sm *= __expf(m - M);
        #pragma unroll
        for (int o = 16; o; o >>= 1) sm += __shfl_xor_sync(~0u, sm, o);
        float inv = 1.f / (sm + 1e-16f);
        for (int basei = 0; basei < deg; basei += 32) {
            int i = basei + lane;
            float alpha = 0.f;
            int src = 0;
            if (i < deg) {
                int sl = d_srcp[beg + i];
                src = b * NPG + sl;
                float lg = ss[src] + sdv + eep[ebase + i];
                lg = lg > 0.f ? lg : 0.2f * lg;
                alpha = __expf(lg - M) * inv;
            }
            int cnt = min(32, deg - basei);
            for (int j = 0; j < cnt; j += 8) {
                #pragma unroll
                for (int q = 0; q < 8; q++) {
                    float A = __shfl_sync(~0u, alpha, j + q);
                    int S   = __shfl_sync(~0u, src, j + q);
                    gatherH<K>(acc, h, S, A, lane);
                }
            }
        }
    }
}

// -------- agg0: gather + ELU + s1 terms; g0 written fp16 ---------------------
__global__ void k_agg0(const float* __restrict__ bias)
{
    int warp = threadIdx.x >> 5, lane = threadIdx.x & 31;
    int n = blockIdx.x * 8 + warp;
    int b = n / NPG, ln = n - b * NPG;
    int beg = d_beg[ln], deg = d_cnt[ln];
    size_t ebase = (size_t)b * EPG + beg;
    float acc[4] = {0.f, 0.f, 0.f, 0.f};
    if (deg > 0)
        agg_core<4>(acc, d_h0, d_s0s, d_ee0p, d_s0d[n], b, beg, deg, ebase, lane);

    float v[4];
    float ps = 0.f, pd = 0.f;
    #pragma unroll
    for (int u = 0; u < 4; u++) {
        float t = acc[u] + bias[lane * 4 + u];
        t = t > 0.f ? t : expm1f(t);
        v[u] = t;
        ps += t * d_was1[lane * 4 + u];
        pd += t * d_wad1[lane * 4 + u];
    }
    #pragma unroll
    for (int o = 16; o; o >>= 1) {
        ps += __shfl_xor_sync(~0u, ps, o);
        pd += __shfl_xor_sync(~0u, pd, o);
    }
    if (lane == 0) { d_s1s[n] = ps; d_s1d[n] = pd; }
    __half2 h01 = __floats2half2_rn(v[0], v[1]);
    __half2 h23 = __floats2half2_rn(v[2], v[3]);
    uint2 u; u.x = *(unsigned*)&h01; u.y = *(unsigned*)&h23;
    *(uint2*)(d_g0h + (size_t)n * 128 + lane * 4) = u;
}

// -------- proj1 via tensor cores: g0h[40000x128] @ W1gT -> h1 fp16 ------------
__global__ void k_proj1mma()
{
    __shared__ __half sW[64 * 136];      // [col][k], padded rows
    __shared__ __half sE[32 * 136];
    int t = threadIdx.x;
    int n0 = blockIdx.x * 32;
    {
        const uint4* src = (const uint4*)d_W1gT;
        uint4* dst = (uint4*)sW;
        for (int i = t; i < 64 * 16; i += 256) {
            int col = i >> 4, ch = i & 15;
            dst[col * 17 + ch] = src[col * 16 + ch];
        }
    }
    {
        const uint4* src = (const uint4*)(d_g0h + (size_t)n0 * 128);
        uint4* dst = (uint4*)sE;
        for (int i = t; i < 32 * 16; i += 256) {
            int row = i >> 4, ch = i & 15;
            dst[row * 17 + ch] = src[row * 16 + ch];
        }
    }
    __syncthreads();

    int warp = t >> 5, lane = t & 31;
    int s = warp & 1;                    // 16-node stripe
    int g = warp >> 1;                   // 16-col group
    int gr = lane >> 2, tc = lane & 3;

    float acc[2][4];
    #pragma unroll
    for (int tt = 0; tt < 2; tt++)
        #pragma unroll
        for (int u = 0; u < 4; u++) acc[tt][u] = 0.f;

    #pragma unroll
    for (int kk = 0; kk < 128; kk += 16) {
        unsigned a0 = *(const unsigned*)(sE + (s * 16 + gr) * 136 + kk + 2 * tc);
        unsigned a1 = *(const unsigned*)(sE + (s * 16 + gr + 8) * 136 + kk + 2 * tc);
        unsigned a2 = *(const unsigned*)(sE + (s * 16 + gr) * 136 + kk + 2 * tc + 8);
        unsigned a3 = *(const unsigned*)(sE + (s * 16 + gr + 8) * 136 + kk + 2 * tc + 8);
        #pragma unroll
        for (int tt = 0; tt < 2; tt++) {
            int col = g * 16 + tt * 8 + gr;
            unsigned b0 = *(const unsigned*)(sW + col * 136 + kk + 2 * tc);
            unsigned b1 = *(const unsigned*)(sW + col * 136 + kk + 2 * tc + 8);
            MMA_FP16(acc[tt], a0, a1, a2, a3, b0, b1);
        }
    }
    #pragma unroll
    for (int tt = 0; tt < 2; tt++) {
        int c = g * 16 + tt * 8 + 2 * tc;
        int r0 = n0 + s * 16 + gr, r1 = r0 + 8;
        __half2 h0 = __floats2half2_rn(acc[tt][0], acc[tt][1]);
        __half2 h1 = __floats2half2_rn(acc[tt][2], acc[tt][3]);
        *(__half2*)(d_h1 + (size_t)r0 * 64 + c) = h0;
        *(__half2*)(d_h1 + (size_t)r1 * 64 + c) = h1;
    }
}

// -------- agg1 fused with pooling partials --------------------------------------
__global__ void k_agg1(const float* __restrict__ bias)
{
    __shared__ float semb[8][64];
    int warp = threadIdx.x >> 5, lane = threadIdx.x & 31;
    int n = blockIdx.x * 8 + warp;
    int b = n / NPG, ln = n - b * NPG;
    int beg = d_beg[ln], deg = d_cnt[ln];
    size_t ebase = (size_t)b * EPG + beg;
    float acc[2] = {0.f, 0.f};
    if (deg > 0)
        agg_core<2>(acc, d_h1, d_s1s, d_ee1p, d_s1d[n], b, beg, deg, ebase, lane);

    float v0 = acc[0] + bias[lane * 2];
    float v1 = acc[1] + bias[lane * 2 + 1];
    float2 f2; f2.x = v0; f2.y = v1;
    *(float2*)(d_emb + (size_t)n * 64 + lane * 2) = f2;
    semb[warp][lane * 2] = v0;
    semb[warp][lane * 2 + 1] = v1;
    __syncthreads();
    int t = threadIdx.x;
    if (t < 64) {
        float s = 0.f, m = -1e30f;
        #pragma unroll
        for (int r = 0; r < 8; r++) {
            float x = semb[r][t];
            s += x; m = fmaxf(m, x);
        }
        d_psum[blockIdx.x * 64 + t] = s;
        d_pmaxf[blockIdx.x * 64 + t] = m;
    }
}

// ------ k_D: hierarchical pooling reduce + ctx GEMM (8 blocks x 1024) --------
__global__ void k_D(const float* __restrict__ W1, const float* __restrict__ b1)
{
    __shared__ float red[1024];
    __shared__ float ctx[128];
    int g = blockIdx.x;
    int t = threadIdx.x;
    int c = t & 63, r = t >> 6;
    float s = 0.f, m = -1e30f;
    for (int i = r; i < 625; i += 16) {
        int idx = (g * 625 + i) * 64 + c;
        s += d_psum[idx];
        m = fmaxf(m, d_pmaxf[idx]);
    }
    red[t] = s;
    __syncthreads();
    for (int rr = 8; rr >= 1; rr >>= 1) {
        if (r < rr) red[t] += red[t + rr * 64];
        __syncthreads();
    }
    if (r == 0) ctx[c] = red[c] * (1.f / NPG);
    __syncthreads();
    red[t] = m;
    __syncthreads();
    for (int rr = 8; rr >= 1; rr >>= 1) {
        if (r < rr) red[t] = fmaxf(red[t], red[t + rr * 64]);
        __syncthreads();
    }
    if (r == 0) ctx[64 + c] = red[c];
    __syncthreads();
    int c2 = t & 127, p = t >> 7;
    float acc = 0.f;
    #pragma unroll
    for (int k = p * 16; k < p * 16 + 16; k++)
        acc += ctx[k] * W1[(144 + k) * 128 + c2];
    red[t] = acc;
    __syncthreads();
    if (p == 0) {
        float tot = b1[c2];
        #pragma unroll
        for (int q = 0; q < 8; q++) tot += red[q * 128 + c2];
        d_D[g * 128 + c2] = tot;
    }
}

// ------ k_AB: tensor-core GEMM emb[40000x64] @ W1hT -> A||B (fp16) -----------
__global__ void k_AB()
{
    __shared__ __half sW[256 * 72];      // [col][k] padded
    __shared__ __half sE[32 * 72];
    int t = threadIdx.x;
    int n0 = blockIdx.x * 32;
    {
        const uint4* src = (const uint4*)d_W1hT;
        uint4* dst = (uint4*)sW;
        for (int i = t; i < 256 * 8; i += 256) {
            int col = i >> 3, ch = i & 7;
            dst[col * 9 + ch] = src[col * 8 + ch];
        }
    }
    {
        const float2* src = (const float2*)(d_emb + (size_t)n0 * 64);
        for (int i = t; i < 32 * 32; i += 256) {
            int row = i >> 5, c2 = i & 31;
            float2 f = src[row * 32 + c2];
            *(__half2*)(sE + row * 72 + c2 * 2) = __floats2half2_rn(f.x, f.y);
        }
    }
    __syncthreads();

    int warp = t >> 5, lane = t & 31;
    int s = warp & 1;
    int g = warp >> 1;
    int gr = lane >> 2, tc = lane & 3;

    float acc[8][4];
    #pragma unroll
    for (int tt = 0; tt < 8; tt++)
        #pragma unroll
        for (int u = 0; u < 4; u++) acc[tt][u] = 0.f;

    #pragma unroll
    for (int kk = 0; kk < 64; kk += 16) {
        unsigned a0 = *(const unsigned*)(sE + (s * 16 + gr) * 72 + kk + 2 * tc);
        unsigned a1 = *(const unsigned*)(sE + (s * 16 + gr + 8) * 72 + kk + 2 * tc);
        unsigned a2 = *(const unsigned*)(sE + (s * 16 + gr) * 72 + kk + 2 * tc + 8);
        unsigned a3 = *(const unsigned*)(sE + (s * 16 + gr + 8) * 72 + kk + 2 * tc + 8);
        #pragma unroll
        for (int tt = 0; tt < 8; tt++) {
            int col = g * 64 + tt * 8 + gr;
            unsigned b0 = *(const unsigned*)(sW + col * 72 + kk + 2 * tc);
            unsigned b1 = *(const unsigned*)(sW + col * 72 + kk + 2 * tc + 8);
            MMA_FP16(acc[tt], a0, a1, a2, a3, b0, b1);
        }
    }
    #pragma unroll
    for (int tt = 0; tt < 8; tt++) {
        int c = g * 64 + tt * 8 + 2 * tc;
        int r0 = n0 + s * 16 + gr, r1 = r0 + 8;
        __half2 h0 = __floats2half2_rn(acc[tt][0], acc[tt][1]);
        __half2 h1 = __floats2half2_rn(acc[tt][2], acc[tt][3]);
        if (c < 128) {
            *(__half2*)(d_A + (size_t)r0 * 128 + c) = h0;
            *(__half2*)(d_A + (size_t)r1 * 128 + c) = h1;
        } else {
            *(__half2*)(d_Bm + (size_t)r0 * 128 + c - 128) = h0;
            *(__half2*)(d_Bm + (size_t)r1 * 128 + c - 128) = h1;
        }
    }
}

// ------ k_final: per dst node, 16-edge mma tiles ------------------------------
__global__ void k_final(const float* __restrict__ W2, const float* __restrict__ b2,
                        float* __restrict__ out)
{
    __shared__ __half sEF[8][256];           // 16 edges x 16 halves per warp
    __shared__ __half sA[8][16 * 136];       // gathered A rows, padded
    __shared__ float  sbase[8][128];         // B[dst]+D per node
    __shared__ float  sV[128];               // W2
    int t = threadIdx.x;
    if (t < 128) sV[t] = W2[t];
    __syncthreads();

    int warp = t >> 5, lane = t & 31;
    int gr = lane >> 2, tc = lane & 3;
    float bias2 = b2[0];

    // hoist W1c mma B-fragments: 32 regs
    unsigned wb[32];
    #pragma unroll
    for (int q = 0; q < 32; q++) wb[q] = d_WBf[q * 32 + lane];

    __half* myEF = sEF[warp];
    __half* myA  = sA[warp];
    float*  myB  = sbase[warp];

    for (int n = blockIdx.x * 8 + warp; n < NN; n += gridDim.x * 8) {
        int b = n / NPG, ln = n - b * NPG;
        int beg = d_beg[ln], deg = d_cnt[ln];
        if (deg == 0) continue;
        int bNPG = b * NPG;
        size_t bEPG = (size_t)b * EPG;
        size_t ebase = bEPG + beg;

        // stage base = B[dst] + D into smem (lane covers cols lane*4..+3)
        {
            int j0 = lane * 4;
            uint2 ub = *(const uint2*)(d_Bm + (size_t)n * 128 + j0);
            float2 blo = __half22float2(*(__half2*)&ub.x);
            float2 bhi = __half22float2(*(__half2*)&ub.y);
            float4 vd = *(const float4*)(d_D + b * 128 + j0);
            float4 bs;
            bs.x = blo.x + vd.x; bs.y = blo.y + vd.y;
            bs.z = bhi.x + vd.z; bs.w = bhi.y + vd.w;
            *(float4*)(myB + j0) = bs;
        }
        __syncwarp();

        for (int i = 0; i < deg; i += 16) {
            // stage ef tile: 16 rows x 32B contiguous = 512B
            {
                uint4 v = *(const uint4*)(d_nefp + (ebase + i) * 16 + lane * 8);
                *(uint4*)(myEF + lane * 8) = v;
            }
            // src indices (lanes 0-15 own rows; clamped)
            int sl = d_srcp[beg + min(i + (lane & 15), deg - 1)];
            __syncwarp();
            // stage A rows: 2 rows per instruction
            #pragma unroll
            for (int j = 0; j < 8; j++) {
                int r = 2 * j + (lane >> 4);
                int sr = __shfl_sync(~0u, sl, r);
                uint4 av = *(const uint4*)(d_A + (size_t)(bNPG + sr) * 128 + (lane & 15) * 8);
                *(uint4*)(myA + r * 136 + (lane & 15) * 8) = av;
            }
            __syncwarp();

            // A fragments from ef tile (rows 32B apart)
            unsigned a0 = *(const unsigned*)(myEF + gr * 16 + 2 * tc);
            unsigned a1 = *(const unsigned*)(myEF + (gr + 8) * 16 + 2 * tc);
            unsigned a2 = *(const unsigned*)(myEF + gr * 16 + 2 * tc + 8);
            unsigned a3 = *(const unsigned*)(myEF + (gr + 8) * 16 + 2 * tc + 8);

            float rowlo = 0.f, rowhi = 0.f;
            #pragma unroll
            for (int nt = 0; nt < 16; nt++) {
                float c[4] = {0.f, 0.f, 0.f, 0.f};
                MMA_FP16(c, a0, a1, a2, a3, wb[nt * 2], wb[nt * 2 + 1]);
                int col = 2 * tc + 8 * nt;
                unsigned alo = *(const unsigned*)(myA + gr * 136 + col);
                unsigned ahi = *(const unsigned*)(myA + (gr + 8) * 136 + col);
                float2 fa = __half22float2(*(__half2*)&alo);
                float2 fh = __half22float2(*(__half2*)&ahi);
                float2 bs = *(const float2*)(myB + col);
                float2 w2 = *(const float2*)(sV + col);
                float v0 = c[0] + fa.x + bs.x;
                float v1 = c[1] + fa.y + bs.y;
                float v2 = c[2] + fh.x + bs.x;
                float v3 = c[3] + fh.y + bs.y;
                rowlo += fmaxf(v0, 0.f) * w2.x + fmaxf(v1, 0.f) * w2.y;
                rowhi += fmaxf(v2, 0.f) * w2.x + fmaxf(v3, 0.f) * w2.y;
            }
            rowlo += __shfl_xor_sync(~0u, rowlo, 1);
            rowlo += __shfl_xor_sync(~0u, rowlo, 2);
            rowhi += __shfl_xor_sync(~0u, rowhi, 1);
            rowhi += __shfl_xor_sync(~0u, rowhi, 2);
            if (tc == 0) {
                int e0 = i + gr, e1 = i + gr + 8;
                if (e0 < deg) out[bEPG + d_csr[beg + e0]] = rowlo + bias2;
                if (e1 < deg) out[bEPG + d_csr[beg + e1]] = rowhi + bias2;
            }
            __syncwarp();
        }
    }
}

// ---------------------------------------------------------------------------
extern "C" void kernel_launch(void* const* d_in, const int* in_sizes, int n_in,
                              void* d_out, int out_size)
{
    const float* node_x    = (const float*)d_in[0];
    const float* edge_attr = (const float*)d_in[1];
    const int*   edge_idx  = (const int*)  d_in[2];
    const float* ln_ng     = (const float*)d_in[3];
    const float* ln_nb     = (const float*)d_in[4];
    const float* ln_eg     = (const float*)d_in[5];
    const float* ln_eb     = (const float*)d_in[6];
    const float* g0_W      = (const float*)d_in[7];
    const float* g0_We     = (const float*)d_in[8];
    const float* g0_asrc   = (const float*)d_in[9];
    const float* g0_adst   = (const float*)d_in[10];
    const float* g0_ae     = (const float*)d_in[11];
    const float* g0_b      = (const float*)d_in[12];
    const float* g1_W      = (const float*)d_in[13];
    const float* g1_We     = (const float*)d_in[14];
    const float* g1_asrc   = (const float*)d_in[15];
    const float* g1_adst   = (const float*)d_in[16];
    const float* g1_ae     = (const float*)d_in[17];
    const float* g1_b      = (const float*)d_in[18];
    const float* mlp_W1    = (const float*)d_in[19];
    const float* mlp_b1    = (const float*)d_in[20];
    const float* mlp_W2    = (const float*)d_in[21];
    const float* mlp_b2    = (const float*)d_in[22];
    float* out = (float*)d_out;

    k_pre<<<40, 256>>>(g0_We, g0_ae, g1_We, g1_ae,
                       g0_W, g0_asrc, g0_adst, g1_W, g1_asrc, g1_adst, mlp_W1);
    k_csr<<<313, 256>>>(edge_idx);
    k_feat<<<7500, 256>>>(edge_attr, ln_eg, ln_eb, node_x, ln_ng, ln_nb, g0_W);
    k_agg0<<<5000, 256>>>(g0_b);           // <- profiled launch slot
    k_proj1mma<<<NN / 32, 256>>>();
    k_agg1<<<5000, 256>>>(g1_b);
    k_D<<<BB, 1024>>>(mlp_W1, mlp_b1);
    k_AB<<<NN / 32, 256>>>();
    k_final<<<1184, 256>>>(mlp_W2, mlp_b2, out);
}